// round 12
// baseline (speedup 1.0000x reference)
#include <cuda_runtime.h>

#define BB 32
#define NN 4096
#define DD 1024
#define HH 16

// Scratch (device globals)
__device__ float  g_qp[4][BB * DD];          // q projection partials over 4 d-ranges
__device__ float  g_Ut[BB * DD * HH];        // folded key vectors, transposed [b][d][h] (scaled 1/8)
__device__ float2 g_stat[BB * HH * 16];      // per-(b,h,256n-tile) (tile max, tile sumexp)
__device__ float  g_wp[16][BB * HH * DD];    // per-tile unnormalized attn@value partials

typedef unsigned long long u64;

__device__ __forceinline__ void fma2(u64 &d, u64 a, u64 b) {
    asm("fma.rn.f32x2 %0, %1, %2, %0;" : "+l"(d) : "l"(a), "l"(b));
}
__device__ __forceinline__ u64 pack2(float lo, float hi) {
    u64 r; asm("mov.b64 %0, {%1, %2};" : "=l"(r) : "f"(lo), "f"(hi)); return r;
}
__device__ __forceinline__ void unpack2(u64 v, float &lo, float &hi) {
    asm("mov.b64 {%0, %1}, %2;" : "=f"(lo), "=f"(hi) : "l"(v));
}
__device__ __forceinline__ unsigned smem_u32(const void* p) {
    return (unsigned)__cvta_generic_to_shared(p);
}
__device__ __forceinline__ void cpasync16(unsigned dst, const void* src) {
    asm volatile("cp.async.cg.shared.global [%0], [%1], 16;\n" :: "r"(dst), "l"(src));
}
#define CP_COMMIT() asm volatile("cp.async.commit_group;\n" ::: "memory")
#define CP_WAIT(n)  asm volatile("cp.async.wait_group %0;\n" :: "n"(n) : "memory")

// ---------------------------------------------------------------------------
// Kernel A: qp[dsp][b,c] = sum_{d in dsp-range(256)} query[b,d] * wq[d,c]
// Also zeroes d_out (256 blocks x 128 threads = 32768 floats exactly).
// ---------------------------------------------------------------------------
__global__ __launch_bounds__(128) void k_qproj(const float* __restrict__ query,
                                               const float* __restrict__ wq,
                                               float* __restrict__ out) {
    const int tx  = threadIdx.x;
    const int c0  = blockIdx.x * 128;
    const int b0  = blockIdx.y * 4;
    const int dsp = blockIdx.z;
    const int dr0 = dsp * 256;

    {
        int lin = blockIdx.x + 8 * blockIdx.y + 64 * blockIdx.z;
        out[lin * 128 + tx] = 0.0f;
    }

    __shared__ __align__(16) float sq[4][256];
#pragma unroll
    for (int i = 0; i < 2; i++) {
        int fl = i * 128 + tx;
        int bb = fl >> 6, d4 = fl & 63;
        *(float4*)&sq[bb][d4 * 4] =
            *(const float4*)(query + (size_t)(b0 + bb) * DD + dr0 + d4 * 4);
    }
    __syncthreads();

    u64 acc[4] = {0ull, 0ull, 0ull, 0ull};
    const float* wc = wq + (size_t)dr0 * DD + c0 + tx;
#pragma unroll 16
    for (int d = 0; d < 256; d += 2) {
        float w0 = wc[(size_t)d * DD];
        float w1 = wc[(size_t)(d + 1) * DD];
        u64 w2 = pack2(w0, w1);
#pragma unroll
        for (int bb = 0; bb < 4; bb++) {
            u64 q2 = *(const u64*)&sq[bb][d];
            fma2(acc[bb], q2, w2);
        }
    }
#pragma unroll
    for (int bb = 0; bb < 4; bb++) {
        float lo, hi; unpack2(acc[bb], lo, hi);
        g_qp[dsp][(size_t)(b0 + bb) * DD + c0 + tx] = lo + hi;
    }
}

// ---------------------------------------------------------------------------
// Kernel B: Ut[b,d,h] = (1/8) * sum_{c<64} wk[d, h*64+c] * q[b, h*64+c]
// ---------------------------------------------------------------------------
__global__ __launch_bounds__(128) void k_uproj(const float* __restrict__ wk) {
    const int tx = threadIdx.x;
    const int d0 = blockIdx.x * 128;
    const int h  = blockIdx.y;
    __shared__ __align__(16) float4 swk4[128 * 17];
    __shared__ __align__(16) float  sq[32][64];

#pragma unroll
    for (int i = 0; i < 16; i++) {
        int fl = i * 128 + tx;
        int r  = fl >> 4, c4 = fl & 15;
        swk4[r * 17 + c4] =
            *(const float4*)(wk + (size_t)(d0 + r) * DD + h * 64 + c4 * 4);
    }
#pragma unroll
    for (int i = 0; i < 4; i++) {
        int fl = i * 128 + tx;
        int bb = fl >> 4, c4 = fl & 15;
        float4 s = *(const float4*)(g_qp[0] + (size_t)bb * DD + h * 64 + c4 * 4);
#pragma unroll
        for (int p = 1; p < 4; p++) {
            float4 a = *(const float4*)(g_qp[p] + (size_t)bb * DD + h * 64 + c4 * 4);
            s.x += a.x; s.y += a.y; s.z += a.z; s.w += a.w;
        }
        *(float4*)&sq[bb][c4 * 4] = s;
    }
    __syncthreads();

    ulonglong2 wreg[16];
#pragma unroll
    for (int c4 = 0; c4 < 16; c4++)
        wreg[c4] = *(const ulonglong2*)&swk4[tx * 17 + c4];

    const int dst_base = (d0 + tx) * HH + h;
#pragma unroll 2
    for (int bb = 0; bb < 32; bb++) {
        u64 a2 = 0ull;
#pragma unroll
        for (int c4 = 0; c4 < 16; c4++) {
            ulonglong2 q2 = *(const ulonglong2*)&sq[bb][c4 * 4];
            fma2(a2, wreg[c4].x, q2.x);
            fma2(a2, wreg[c4].y, q2.y);
        }
        float lo, hi; unpack2(a2, lo, hi);
        g_Ut[(size_t)bb * (DD * HH) + dst_base] = (lo + hi) * 0.125f;
    }
}

// ---------------------------------------------------------------------------
// Kernel C (FUSED flash-style): per (b, 256-n tile) CTA:
//   Phase 1: scores s[h,n] = sum_d key[n,d]*Ut[d,h]  (R5-proven per-warp
//            cp.async pattern: 4 warps x 64 n, d-chunk 8, warp-sync only)
//   Stats:   CTA-tile max m_t[h], p = exp(s - m_t) -> smem slab sA[256][16],
//            tile sumexp s_t[h]; (m_t, s_t) -> g_stat.
//   Phase 2: partial[h,d] = sum_n p[n,h]*value[n,d]  (R11-proven thread-
//            private cp.async value columns; 2 sequential d-halves of 512)
// g_att round-trip eliminated. smem = exactly 48KB static (unioned).
// ---------------------------------------------------------------------------
__global__ __launch_bounds__(128, 4) void k_attn(const float* __restrict__ key,
                                                 const float* __restrict__ value) {
    const int tx   = threadIdx.x;
    const int w    = tx >> 5;
    const int l    = tx & 31;
    const int b    = blockIdx.y;
    const int seg  = blockIdx.x;       // 16 tiles of 256 n
    const int n0   = seg * 256;
    const int nwrp = n0 + w * 64;

    __shared__ __align__(16) char smem_raw[49152];
    float4* skW   = (float4*)smem_raw;               // [4w][2st][192]  24576B
    float4* sUW   = (float4*)(smem_raw + 24576);     // [4w][2st][32]    4096B
    float*  sRedM = (float*)(smem_raw + 28672);      // [4w][16]          256B
    float*  sRedS = (float*)(smem_raw + 28928);      // [4w][16]          256B
    float4* sV    = (float4*)smem_raw;               // union [2st][8][128] 32768B
    float*  sA    = (float*)(smem_raw + 32768);      // [256][16]       16384B

    const float* keyw = key + ((size_t)b * NN + nwrp) * DD;
    const float* Utb  = g_Ut + (size_t)b * (DD * HH);

    // ================= Phase 1: scores =================
    u64 acc_a[8], acc_b[8];
#pragma unroll
    for (int p = 0; p < 8; p++) { acc_a[p] = 0ull; acc_b[p] = 0ull; }

    // prologue chunk 0 (d 0..7)
    {
#pragma unroll
        for (int i = 0; i < 4; i++) {
            int fl = i * 32 + l;
            int n = fl >> 1, q4 = fl & 1;
            cpasync16(smem_u32(&skW[(w * 2 + 0) * 192 + n * 3 + q4]),
                      keyw + (size_t)n * DD + q4 * 4);
        }
        cpasync16(smem_u32(&sUW[(w * 2 + 0) * 32 + l]), Utb + l * 4);
        CP_COMMIT();
    }

#pragma unroll 1
    for (int ch = 0; ch < 128; ch++) {
        if (ch + 1 < 128) {
            const int st = (ch + 1) & 1, d0 = (ch + 1) * 8;
#pragma unroll
            for (int i = 0; i < 4; i++) {
                int fl = i * 32 + l;
                int n = fl >> 1, q4 = fl & 1;
                cpasync16(smem_u32(&skW[(w * 2 + st) * 192 + n * 3 + q4]),
                          keyw + (size_t)n * DD + d0 + q4 * 4);
            }
            cpasync16(smem_u32(&sUW[(w * 2 + st) * 32 + l]), Utb + d0 * HH + l * 4);
            CP_COMMIT();
            CP_WAIT(1);
        } else {
            CP_WAIT(0);
        }
        __syncwarp();

        const int st = ch & 1;
        float4 ka0 = skW[(w * 2 + st) * 192 + l * 3 + 0];
        float4 ka1 = skW[(w * 2 + st) * 192 + l * 3 + 1];
        float4 kb0 = skW[(w * 2 + st) * 192 + (l + 32) * 3 + 0];
        float4 kb1 = skW[(w * 2 + st) * 192 + (l + 32) * 3 + 1];
        float kas[8] = {ka0.x, ka0.y, ka0.z, ka0.w, ka1.x, ka1.y, ka1.z, ka1.w};
        float kbs[8] = {kb0.x, kb0.y, kb0.z, kb0.w, kb1.x, kb1.y, kb1.z, kb1.w};
#pragma unroll
        for (int dd = 0; dd < 8; dd++) {
            u64 kva = pack2(kas[dd], kas[dd]);
            u64 kvb = pack2(kbs[dd], kbs[dd]);
            const ulonglong2* uv = (const ulonglong2*)&sUW[(w * 2 + st) * 32 + dd * 4];
            ulonglong2 u0 = uv[0], u1 = uv[1];
            fma2(acc_a[0], u0.x, kva);  fma2(acc_b[0], u0.x, kvb);
            fma2(acc_a[1], u0.y, kva);  fma2(acc_b[1], u0.y, kvb);
            fma2(acc_a[2], u1.x, kva);  fma2(acc_b[2], u1.x, kvb);
            fma2(acc_a[3], u1.y, kva);  fma2(acc_b[3], u1.y, kvb);
            ulonglong2 u2 = uv[2], u3 = uv[3];
            fma2(acc_a[4], u2.x, kva);  fma2(acc_b[4], u2.x, kvb);
            fma2(acc_a[5], u2.y, kva);  fma2(acc_b[5], u2.y, kvb);
            fma2(acc_a[6], u3.x, kva);  fma2(acc_b[6], u3.x, kvb);
            fma2(acc_a[7], u3.y, kva);  fma2(acc_b[7], u3.y, kvb);
        }
        __syncwarp();
    }

    // ================= Stats + exp slab =================
    float mt[16];
#pragma unroll
    for (int h = 0; h < 16; h++) mt[h] = -3e38f;
#pragma unroll
    for (int p = 0; p < 8; p++) {
        float lo, hi;
        unpack2(acc_a[p], lo, hi);
        mt[2 * p] = fmaxf(mt[2 * p], lo);  mt[2 * p + 1] = fmaxf(mt[2 * p + 1], hi);
        unpack2(acc_b[p], lo, hi);
        mt[2 * p] = fmaxf(mt[2 * p], lo);  mt[2 * p + 1] = fmaxf(mt[2 * p + 1], hi);
    }
#pragma unroll
    for (int h = 0; h < 16; h++)
#pragma unroll
        for (int o = 16; o; o >>= 1)
            mt[h] = fmaxf(mt[h], __shfl_xor_sync(0xffffffffu, mt[h], o));
    if (l == 0) {
#pragma unroll
        for (int h = 0; h < 16; h++) sRedM[w * 16 + h] = mt[h];
    }
    __syncthreads();

    float cm[16];
#pragma unroll
    for (int h = 0; h < 16; h++)
        cm[h] = fmaxf(fmaxf(sRedM[h], sRedM[16 + h]),
                      fmaxf(sRedM[32 + h], sRedM[48 + h]));

    float ssum[16];
#pragma unroll
    for (int h = 0; h < 16; h++) ssum[h] = 0.f;
    {
        const int na = w * 64 + l, nb = na + 32;
#pragma unroll
        for (int p = 0; p < 8; p++) {
            float lo, hi;
            unpack2(acc_a[p], lo, hi);
            float e0 = __expf(lo - cm[2 * p]);
            float e1 = __expf(hi - cm[2 * p + 1]);
            ssum[2 * p] += e0; ssum[2 * p + 1] += e1;
            *(u64*)(sA + na * 16 + 2 * p) = pack2(e0, e1);
            unpack2(acc_b[p], lo, hi);
            e0 = __expf(lo - cm[2 * p]);
            e1 = __expf(hi - cm[2 * p + 1]);
            ssum[2 * p] += e0; ssum[2 * p + 1] += e1;
            *(u64*)(sA + nb * 16 + 2 * p) = pack2(e0, e1);
        }
    }
#pragma unroll
    for (int h = 0; h < 16; h++)
#pragma unroll
        for (int o = 16; o; o >>= 1)
            ssum[h] += __shfl_xor_sync(0xffffffffu, ssum[h], o);
    if (l == 0) {
#pragma unroll
        for (int h = 0; h < 16; h++) sRedS[w * 16 + h] = ssum[h];
    }
    __syncthreads();

    if (tx < 16) {
        float s_t = sRedS[tx] + sRedS[16 + tx] + sRedS[32 + tx] + sRedS[48 + tx];
        g_stat[((size_t)b * HH + tx) * 16 + seg] = make_float2(cm[tx], s_t);
    }
    __syncthreads();   // sRedS reads done before sV (union) is written; sA final

    // ================= Phase 2: partial attn @ value =================
#pragma unroll 1
    for (int half = 0; half < 2; half++) {
        u64 acc[32];
#pragma unroll
        for (int p = 0; p < 32; p++) acc[p] = 0ull;

        const float* valb = value + ((size_t)b * NN + n0) * DD + half * 512 + tx * 4;

#pragma unroll
        for (int j = 0; j < 8; j++)
            cpasync16(smem_u32(&sV[(0 * 8 + j) * 128 + tx]), valb + (size_t)j * DD);
        CP_COMMIT();

#pragma unroll 1
        for (int ch = 0; ch < 32; ch++) {
            if (ch + 1 < 32) {
                const int st = (ch + 1) & 1;
                const float* src = valb + (size_t)(ch + 1) * 8 * DD;
#pragma unroll
                for (int j = 0; j < 8; j++)
                    cpasync16(smem_u32(&sV[(st * 8 + j) * 128 + tx]), src + (size_t)j * DD);
                CP_COMMIT();
                CP_WAIT(1);
            } else {
                CP_WAIT(0);
            }
            // no barrier: sV words are thread-private; sA is read-only broadcast

            const int st = ch & 1;
            const float* sArow = sA + (ch * 8) * 16;
#pragma unroll
            for (int j = 0; j < 8; j++) {
                float4 v4 = sV[(st * 8 + j) * 128 + tx];
                float vs[4] = {v4.x, v4.y, v4.z, v4.w};
                const ulonglong2* av = (const ulonglong2*)(sArow + j * 16);
                ulonglong2 a0 = av[0], a1 = av[1], a2 = av[2], a3 = av[3];
#pragma unroll
                for (int dd = 0; dd < 4; dd++) {
                    u64 v2 = pack2(vs[dd], vs[dd]);
                    fma2(acc[dd * 8 + 0], a0.x, v2);
                    fma2(acc[dd * 8 + 1], a0.y, v2);
                    fma2(acc[dd * 8 + 2], a1.x, v2);
                    fma2(acc[dd * 8 + 3], a1.y, v2);
                    fma2(acc[dd * 8 + 4], a2.x, v2);
                    fma2(acc[dd * 8 + 5], a2.y, v2);
                    fma2(acc[dd * 8 + 6], a3.x, v2);
                    fma2(acc[dd * 8 + 7], a3.y, v2);
                }
            }
        }

#pragma unroll
        for (int hp = 0; hp < 8; hp++) {
            float l0, h0x, l1, h1x, l2, h2x, l3, h3x;
            unpack2(acc[0 * 8 + hp], l0, h0x);
            unpack2(acc[1 * 8 + hp], l1, h1x);
            unpack2(acc[2 * 8 + hp], l2, h2x);
            unpack2(acc[3 * 8 + hp], l3, h3x);
            float4 olo = make_float4(l0, l1, l2, l3);
            float4 ohi = make_float4(h0x, h1x, h2x, h3x);
            *(float4*)(g_wp[seg] + ((size_t)b * HH + 2 * hp)     * DD + half * 512 + tx * 4) = olo;
            *(float4*)(g_wp[seg] + ((size_t)b * HH + 2 * hp + 1) * DD + half * 512 + tx * 4) = ohi;
        }
    }
}

// ---------------------------------------------------------------------------
// Kernel F: out[b,c] += sum_{d in dsp-range(256)} w[b, c>>6, d] * wv[d, c]
// where w = sum_t g_wp[t] * exp(m_t - m_g) / s_g  (flash rescale-combine)
// ---------------------------------------------------------------------------
__global__ __launch_bounds__(128) void k_oproj(const float* __restrict__ wv,
                                               float* __restrict__ out) {
    const int tx  = threadIdx.x;
    const int c0  = blockIdx.x * 128;
    const int b0  = blockIdx.y * 4;
    const int dsp = blockIdx.z;
    const int dr0 = dsp * 256;
    const int h0  = c0 >> 6;
    __shared__ __align__(16) float sw[4][2][256];
    __shared__ float sScale[4][2][16];

    // per-(b,h) combine scales: 8 rows x 16 tiles, one thread per (row, tile)
    {
        int row = tx >> 4;            // 0..7  (bb*2 + hh)
        int t   = tx & 15;
        int bb  = row >> 1, hh = row & 1;
        const float2* gs = g_stat + ((size_t)(b0 + bb) * HH + h0 + hh) * 16;
        float m = -3e38f;
#pragma unroll
        for (int k = 0; k < 16; k++) m = fmaxf(m, gs[k].x);
        float s = 0.f;
#pragma unroll
        for (int k = 0; k < 16; k++) s += gs[k].y * __expf(gs[k].x - m);
        sScale[bb][hh][t] = __expf(gs[t].x - m) / s;
    }
    __syncthreads();

#pragma unroll
    for (int i = 0; i < 4; i++) {
        int fl = i * 128 + tx;
        int bb = fl >> 7, hh = (fl >> 6) & 1, d4 = fl & 63;
        size_t gidx = ((size_t)(b0 + bb) * HH + h0 + hh) * DD + dr0 + d4 * 4;
        float4 s = make_float4(0.f, 0.f, 0.f, 0.f);
#pragma unroll
        for (int t = 0; t < 16; t++) {
            float sc = sScale[bb][hh][t];
            float4 a = *(const float4*)(g_wp[t] + gidx);
            s.x += a.x * sc; s.y += a.y * sc; s.z += a.z * sc; s.w += a.w * sc;
        }
        *(float4*)&sw[bb][hh][d4 * 4] = s;
    }
    __syncthreads();

    const int hin = tx >> 6;
    u64 acc[4] = {0ull, 0ull, 0ull, 0ull};
    const float* wc = wv + (size_t)dr0 * DD + c0 + tx;
#pragma unroll 16
    for (int dd = 0; dd < 256; dd += 2) {
        float w0 = wc[(size_t)dd * DD];
        float w1 = wc[(size_t)(dd + 1) * DD];
        u64 w2 = pack2(w0, w1);
#pragma unroll
        for (int bb = 0; bb < 4; bb++) {
            u64 s2 = *(const u64*)&sw[bb][hin][dd];
            fma2(acc[bb], s2, w2);
        }
    }
#pragma unroll
    for (int bb = 0; bb < 4; bb++) {
        float lo, hi; unpack2(acc[bb], lo, hi);
        atomicAdd(&out[(size_t)(b0 + bb) * DD + c0 + tx], lo + hi);
    }
}

// ---------------------------------------------------------------------------
extern "C" void kernel_launch(void* const* d_in, const int* in_sizes, int n_in,
                              void* d_out, int out_size) {
    const float* query = (const float*)d_in[0];
    const float* key   = (const float*)d_in[1];
    const float* value = (const float*)d_in[2];
    const float* wq    = (const float*)d_in[3];
    const float* wk    = (const float*)d_in[4];
    const float* wv    = (const float*)d_in[5];
    float* out = (float*)d_out;

    k_qproj <<<dim3(8, 8, 4), 128>>>(query, wq, out);
    k_uproj <<<dim3(8, HH),   128>>>(wk);
    k_attn  <<<dim3(16, BB),  128>>>(key, value);
    k_oproj <<<dim3(8, 8, 4), 128>>>(wv, out);
}

// round 13
// speedup vs baseline: 1.0718x; 1.0718x over previous
#include <cuda_runtime.h>

#define BB 32
#define NN 4096
#define DD 1024
#define HH 16

// Scratch (device globals)
__device__ float  g_qp[4][BB * DD];          // q projection partials over 4 d-ranges
__device__ float  g_Ut[BB * DD * HH];        // folded key vectors, transposed [b][d][h] (scaled 1/8)
__device__ float  g_att[BB * HH * NN];       // RAW scores
__device__ float2 g_stat[BB * HH * 32];      // per-(b,h,128n-tile) (max, sumexp)
__device__ float  g_wp[8][BB * HH * DD];     // normalized attn@value partials over 8 n-segments

typedef unsigned long long u64;

__device__ __forceinline__ void fma2(u64 &d, u64 a, u64 b) {
    asm("fma.rn.f32x2 %0, %1, %2, %0;" : "+l"(d) : "l"(a), "l"(b));
}
__device__ __forceinline__ u64 pack2(float lo, float hi) {
    u64 r; asm("mov.b64 %0, {%1, %2};" : "=l"(r) : "f"(lo), "f"(hi)); return r;
}
__device__ __forceinline__ void unpack2(u64 v, float &lo, float &hi) {
    asm("mov.b64 {%0, %1}, %2;" : "=f"(lo), "=f"(hi) : "l"(v));
}
__device__ __forceinline__ unsigned smem_u32(const void* p) {
    return (unsigned)__cvta_generic_to_shared(p);
}
__device__ __forceinline__ void cpasync16(unsigned dst, const void* src) {
    asm volatile("cp.async.cg.shared.global [%0], [%1], 16;\n" :: "r"(dst), "l"(src));
}
#define CP_COMMIT() asm volatile("cp.async.commit_group;\n" ::: "memory")
#define CP_WAIT(n)  asm volatile("cp.async.wait_group %0;\n" :: "n"(n) : "memory")

// ---------------------------------------------------------------------------
// Kernel A: qp[dsp][b,c] = sum_{d in dsp-range(256)} query[b,d] * wq[d,c]
// Also zeroes d_out (256 blocks x 128 threads = 32768 floats exactly).
// ---------------------------------------------------------------------------
__global__ __launch_bounds__(128) void k_qproj(const float* __restrict__ query,
                                               const float* __restrict__ wq,
                                               float* __restrict__ out) {
    const int tx  = threadIdx.x;
    const int c0  = blockIdx.x * 128;
    const int b0  = blockIdx.y * 4;
    const int dsp = blockIdx.z;
    const int dr0 = dsp * 256;

    {
        int lin = blockIdx.x + 8 * blockIdx.y + 64 * blockIdx.z;
        out[lin * 128 + tx] = 0.0f;
    }

    __shared__ __align__(16) float sq[4][256];
#pragma unroll
    for (int i = 0; i < 2; i++) {
        int fl = i * 128 + tx;
        int bb = fl >> 6, d4 = fl & 63;
        *(float4*)&sq[bb][d4 * 4] =
            *(const float4*)(query + (size_t)(b0 + bb) * DD + dr0 + d4 * 4);
    }
    __syncthreads();

    u64 acc[4] = {0ull, 0ull, 0ull, 0ull};
    const float* wc = wq + (size_t)dr0 * DD + c0 + tx;
#pragma unroll 16
    for (int d = 0; d < 256; d += 2) {
        float w0 = wc[(size_t)d * DD];
        float w1 = wc[(size_t)(d + 1) * DD];
        u64 w2 = pack2(w0, w1);
#pragma unroll
        for (int bb = 0; bb < 4; bb++) {
            u64 q2 = *(const u64*)&sq[bb][d];
            fma2(acc[bb], q2, w2);
        }
    }
#pragma unroll
    for (int bb = 0; bb < 4; bb++) {
        float lo, hi; unpack2(acc[bb], lo, hi);
        g_qp[dsp][(size_t)(b0 + bb) * DD + c0 + tx] = lo + hi;
    }
}

// ---------------------------------------------------------------------------
// Kernel B: Ut[b,d,h] = (1/8) * sum_{c<64} wk[d, h*64+c] * q[b, h*64+c]
// ---------------------------------------------------------------------------
__global__ __launch_bounds__(128) void k_uproj(const float* __restrict__ wk) {
    const int tx = threadIdx.x;
    const int d0 = blockIdx.x * 128;
    const int h  = blockIdx.y;
    __shared__ __align__(16) float4 swk4[128 * 17];
    __shared__ __align__(16) float  sq[32][64];

#pragma unroll
    for (int i = 0; i < 16; i++) {
        int fl = i * 128 + tx;
        int r  = fl >> 4, c4 = fl & 15;
        swk4[r * 17 + c4] =
            *(const float4*)(wk + (size_t)(d0 + r) * DD + h * 64 + c4 * 4);
    }
#pragma unroll
    for (int i = 0; i < 4; i++) {
        int fl = i * 128 + tx;
        int bb = fl >> 4, c4 = fl & 15;
        float4 s = *(const float4*)(g_qp[0] + (size_t)bb * DD + h * 64 + c4 * 4);
#pragma unroll
        for (int p = 1; p < 4; p++) {
            float4 a = *(const float4*)(g_qp[p] + (size_t)bb * DD + h * 64 + c4 * 4);
            s.x += a.x; s.y += a.y; s.z += a.z; s.w += a.w;
        }
        *(float4*)&sq[bb][c4 * 4] = s;
    }
    __syncthreads();

    ulonglong2 wreg[16];
#pragma unroll
    for (int c4 = 0; c4 < 16; c4++)
        wreg[c4] = *(const ulonglong2*)&swk4[tx * 17 + c4];

    const int dst_base = (d0 + tx) * HH + h;
#pragma unroll 2
    for (int bb = 0; bb < 32; bb++) {
        u64 a2 = 0ull;
#pragma unroll
        for (int c4 = 0; c4 < 16; c4++) {
            ulonglong2 q2 = *(const ulonglong2*)&sq[bb][c4 * 4];
            fma2(a2, wreg[c4].x, q2.x);
            fma2(a2, wreg[c4].y, q2.y);
        }
        float lo, hi; unpack2(a2, lo, hi);
        g_Ut[(size_t)bb * (DD * HH) + dst_base] = (lo + hi) * 0.125f;
    }
}

// ---------------------------------------------------------------------------
// Kernel C: raw scores + per-warp-tile softmax stats. (R11 proven, unchanged)
// ---------------------------------------------------------------------------
__global__ __launch_bounds__(64, 5) void k_scores(const float* __restrict__ key) {
    const int tx   = threadIdx.x;
    const int w    = tx >> 5;
    const int l    = tx & 31;
    const int b    = blockIdx.y;
    const int n0   = blockIdx.x * 256;
    const int nwrp = n0 + w * 128;

    __shared__ __align__(16) float4 skW[2][2][128 * 5];
    __shared__ __align__(16) float4 sUW[2][2][64];

    const float* keyw = key + ((size_t)b * NN + nwrp) * DD;
    const float* Utb  = g_Ut + (size_t)b * (DD * HH);

    u64 acc[4][8];
#pragma unroll
    for (int n4 = 0; n4 < 4; n4++)
#pragma unroll
        for (int p = 0; p < 8; p++) acc[n4][p] = 0ull;

    {
#pragma unroll
        for (int i = 0; i < 16; i++) {
            int fl = i * 32 + l;
            int n = fl >> 2, q4 = fl & 3;
            cpasync16(smem_u32(&skW[w][0][n * 5 + q4]),
                      keyw + (size_t)n * DD + q4 * 4);
        }
#pragma unroll
        for (int j = 0; j < 2; j++)
            cpasync16(smem_u32(&sUW[w][0][j * 32 + l]), Utb + (j * 32 + l) * 4);
        CP_COMMIT();
    }

#pragma unroll 1
    for (int ch = 0; ch < 64; ch++) {
        if (ch + 1 < 64) {
            const int st = (ch + 1) & 1, d0 = (ch + 1) * 16;
#pragma unroll
            for (int i = 0; i < 16; i++) {
                int fl = i * 32 + l;
                int n = fl >> 2, q4 = fl & 3;
                cpasync16(smem_u32(&skW[w][st][n * 5 + q4]),
                          keyw + (size_t)n * DD + d0 + q4 * 4);
            }
#pragma unroll
            for (int j = 0; j < 2; j++)
                cpasync16(smem_u32(&sUW[w][st][j * 32 + l]),
                          Utb + d0 * HH + (j * 32 + l) * 4);
            CP_COMMIT();
            CP_WAIT(1);
        } else {
            CP_WAIT(0);
        }
        __syncwarp();

        const int st = ch & 1;
#pragma unroll
        for (int g = 0; g < 4; g++) {
            float4 kv[4];
#pragma unroll
            for (int n4 = 0; n4 < 4; n4++)
                kv[n4] = skW[w][st][(n4 * 32 + l) * 5 + g];
#pragma unroll
            for (int s = 0; s < 4; s++) {
                int dd = g * 4 + s;
                const ulonglong2* uv = (const ulonglong2*)&sUW[w][st][dd * 4];
                ulonglong2 u0 = uv[0], u1 = uv[1];
                ulonglong2 u2 = uv[2], u3 = uv[3];
#pragma unroll
                for (int n4 = 0; n4 < 4; n4++) {
                    float kvs = (s == 0) ? kv[n4].x : (s == 1) ? kv[n4].y
                              : (s == 2) ? kv[n4].z : kv[n4].w;
                    u64 kv2 = pack2(kvs, kvs);
                    fma2(acc[n4][0], u0.x, kv2);
                    fma2(acc[n4][1], u0.y, kv2);
                    fma2(acc[n4][2], u1.x, kv2);
                    fma2(acc[n4][3], u1.y, kv2);
                    fma2(acc[n4][4], u2.x, kv2);
                    fma2(acc[n4][5], u2.y, kv2);
                    fma2(acc[n4][6], u3.x, kv2);
                    fma2(acc[n4][7], u3.y, kv2);
                }
            }
        }
        __syncwarp();
    }

#pragma unroll
    for (int n4 = 0; n4 < 4; n4++) {
#pragma unroll
        for (int p = 0; p < 8; p++) {
            float lo, hi;
            unpack2(acc[n4][p], lo, hi);
            g_att[((size_t)b * HH + 2 * p)     * NN + nwrp + n4 * 32 + l] = lo;
            g_att[((size_t)b * HH + 2 * p + 1) * NN + nwrp + n4 * 32 + l] = hi;
        }
    }

    float mt[16];
#pragma unroll
    for (int h = 0; h < 16; h++) mt[h] = -3e38f;
#pragma unroll
    for (int n4 = 0; n4 < 4; n4++)
#pragma unroll
        for (int p = 0; p < 8; p++) {
            float lo, hi; unpack2(acc[n4][p], lo, hi);
            mt[2 * p]     = fmaxf(mt[2 * p], lo);
            mt[2 * p + 1] = fmaxf(mt[2 * p + 1], hi);
        }
#pragma unroll
    for (int h = 0; h < 16; h++)
#pragma unroll
        for (int o = 16; o; o >>= 1)
            mt[h] = fmaxf(mt[h], __shfl_xor_sync(0xffffffffu, mt[h], o));

    float st[16];
#pragma unroll
    for (int h = 0; h < 16; h++) st[h] = 0.f;
#pragma unroll
    for (int n4 = 0; n4 < 4; n4++)
#pragma unroll
        for (int p = 0; p < 8; p++) {
            float lo, hi; unpack2(acc[n4][p], lo, hi);
            st[2 * p]     += __expf(lo - mt[2 * p]);
            st[2 * p + 1] += __expf(hi - mt[2 * p + 1]);
        }
#pragma unroll
    for (int h = 0; h < 16; h++)
#pragma unroll
        for (int o = 16; o; o >>= 1)
            st[h] += __shfl_xor_sync(0xffffffffu, st[h], o);

    if (l == 0) {
        int wtile = blockIdx.x * 2 + w;
#pragma unroll
        for (int h = 0; h < 16; h++)
            g_stat[((size_t)b * HH + h) * 32 + wtile] = make_float2(mt[h], st[h]);
    }
}

// ---------------------------------------------------------------------------
// Kernel E: wp[seg][b,h,d] = sum_{n in seg(512)} attn[b,h,n]*value[b,n,d]
// (R11 proven, unchanged) Softmax applied during att staging from tile stats.
// Value via cp.async double buffer; no barriers in the mainloop.
// ---------------------------------------------------------------------------
__global__ __launch_bounds__(128, 3) void k_wpart(const float* __restrict__ value) {
    const int tx  = threadIdx.x;
    const int d0  = blockIdx.x * 512;
    const int seg = blockIdx.y;
    const int b   = blockIdx.z;

    __shared__ __align__(16) float  sA[512 * 20];    // [n][16h + 4 pad], 40KB
    __shared__ __align__(16) float4 sV[2][8][128];   // 2 stages x 8n x 512d, 32KB
    __shared__ float2 sMS[16];                       // (m_glob, 1/s_glob) per head

    if (tx < 16) {
        const float2* gs = g_stat + ((size_t)b * HH + tx) * 32;
        float m = -3e38f;
#pragma unroll
        for (int t = 0; t < 32; t++) m = fmaxf(m, gs[t].x);
        float s = 0.f;
#pragma unroll
        for (int t = 0; t < 32; t++) {
            float2 p = gs[t];
            s += p.y * __expf(p.x - m);
        }
        sMS[tx] = make_float2(m, 1.f / s);
    }

    const float* valb = value + ((size_t)b * NN + seg * 512) * DD + d0 + tx * 4;

#pragma unroll
    for (int j = 0; j < 8; j++)
        cpasync16(smem_u32(&sV[0][j][tx]), valb + (size_t)j * DD);
    CP_COMMIT();

    __syncthreads();   // sMS ready

    const float* attb = g_att + (size_t)b * HH * NN + seg * 512;
#pragma unroll
    for (int i = 0; i < 16; i++) {
        int fl = i * 128 + tx;
        int h = fl >> 7, n4 = (fl & 127) * 4;
        float4 a = *(const float4*)(attb + (size_t)h * NN + n4);
        float2 ms = sMS[h];
        sA[(n4 + 0) * 20 + h] = __expf(a.x - ms.x) * ms.y;
        sA[(n4 + 1) * 20 + h] = __expf(a.y - ms.x) * ms.y;
        sA[(n4 + 2) * 20 + h] = __expf(a.z - ms.x) * ms.y;
        sA[(n4 + 3) * 20 + h] = __expf(a.w - ms.x) * ms.y;
    }
    __syncthreads();

    u64 acc[32];
#pragma unroll
    for (int p = 0; p < 32; p++) acc[p] = 0ull;

#pragma unroll 1
    for (int ch = 0; ch < 64; ch++) {
        if (ch + 1 < 64) {
            const int st = (ch + 1) & 1;
            const float* src = valb + (size_t)(ch + 1) * 8 * DD;
#pragma unroll
            for (int j = 0; j < 8; j++)
                cpasync16(smem_u32(&sV[st][j][tx]), src + (size_t)j * DD);
            CP_COMMIT();
            CP_WAIT(1);
        } else {
            CP_WAIT(0);
        }
        // no barrier: this thread reads only the words it copied itself

        const int st = ch & 1;
        const float* sArow = &sA[ch * 8 * 20];
#pragma unroll
        for (int j = 0; j < 8; j++) {
            float4 v4 = sV[st][j][tx];
            float vs[4] = {v4.x, v4.y, v4.z, v4.w};
            const ulonglong2* av = (const ulonglong2*)(sArow + j * 20);
            ulonglong2 a0 = av[0], a1 = av[1], a2 = av[2], a3 = av[3];
#pragma unroll
            for (int dd = 0; dd < 4; dd++) {
                u64 v2 = pack2(vs[dd], vs[dd]);
                fma2(acc[dd * 8 + 0], a0.x, v2);
                fma2(acc[dd * 8 + 1], a0.y, v2);
                fma2(acc[dd * 8 + 2], a1.x, v2);
                fma2(acc[dd * 8 + 3], a1.y, v2);
                fma2(acc[dd * 8 + 4], a2.x, v2);
                fma2(acc[dd * 8 + 5], a2.y, v2);
                fma2(acc[dd * 8 + 6], a3.x, v2);
                fma2(acc[dd * 8 + 7], a3.y, v2);
            }
        }
    }

#pragma unroll
    for (int hp = 0; hp < 8; hp++) {
        float l0, h0x, l1, h1x, l2, h2x, l3, h3x;
        unpack2(acc[0 * 8 + hp], l0, h0x);
        unpack2(acc[1 * 8 + hp], l1, h1x);
        unpack2(acc[2 * 8 + hp], l2, h2x);
        unpack2(acc[3 * 8 + hp], l3, h3x);
        float4 olo = make_float4(l0, l1, l2, l3);
        float4 ohi = make_float4(h0x, h1x, h2x, h3x);
        *(float4*)(g_wp[seg] + ((size_t)b * HH + 2 * hp)     * DD + d0 + tx * 4) = olo;
        *(float4*)(g_wp[seg] + ((size_t)b * HH + 2 * hp + 1) * DD + d0 + tx * 4) = ohi;
    }
}

// ---------------------------------------------------------------------------
// Kernel F: out[b,c] += sum_{d in dsp-range(128)} w[b, c>>6, d] * wv[d, c]
// d-split 8 (was 4): grid 512 blocks -> ~3.5 CTAs/SM for the latency-bound tail.
// ---------------------------------------------------------------------------
__global__ __launch_bounds__(128) void k_oproj(const float* __restrict__ wv,
                                               float* __restrict__ out) {
    const int tx  = threadIdx.x;
    const int c0  = blockIdx.x * 128;
    const int b0  = blockIdx.y * 4;
    const int dsp = blockIdx.z;
    const int dr0 = dsp * 128;
    const int h0  = c0 >> 6;
    __shared__ __align__(16) float sw[4][2][128];

#pragma unroll
    for (int i = 0; i < 2; i++) {
        int fl = i * 128 + tx;                 // 256 float4 total
        int bb = fl >> 6, hh = (fl >> 5) & 1, d4 = fl & 31;
        size_t gidx = ((size_t)(b0 + bb) * HH + h0 + hh) * DD + dr0 + d4 * 4;
        float4 s = *(const float4*)(g_wp[0] + gidx);
#pragma unroll
        for (int p = 1; p < 8; p++) {
            float4 a = *(const float4*)(g_wp[p] + gidx);
            s.x += a.x; s.y += a.y; s.z += a.z; s.w += a.w;
        }
        *(float4*)&sw[bb][hh][d4 * 4] = s;
    }
    __syncthreads();

    const int hin = tx >> 6;
    u64 acc[4] = {0ull, 0ull, 0ull, 0ull};
    const float* wc = wv + (size_t)dr0 * DD + c0 + tx;
#pragma unroll 16
    for (int dd = 0; dd < 128; dd += 2) {
        float w0 = wc[(size_t)dd * DD];
        float w1 = wc[(size_t)(dd + 1) * DD];
        u64 w2 = pack2(w0, w1);
#pragma unroll
        for (int bb = 0; bb < 4; bb++) {
            u64 s2 = *(const u64*)&sw[bb][hin][dd];
            fma2(acc[bb], s2, w2);
        }
    }
#pragma unroll
    for (int bb = 0; bb < 4; bb++) {
        float lo, hi; unpack2(acc[bb], lo, hi);
        atomicAdd(&out[(size_t)(b0 + bb) * DD + c0 + tx], lo + hi);
    }
}

// ---------------------------------------------------------------------------
extern "C" void kernel_launch(void* const* d_in, const int* in_sizes, int n_in,
                              void* d_out, int out_size) {
    const float* query = (const float*)d_in[0];
    const float* key   = (const float*)d_in[1];
    const float* value = (const float*)d_in[2];
    const float* wq    = (const float*)d_in[3];
    const float* wk    = (const float*)d_in[4];
    const float* wv    = (const float*)d_in[5];
    float* out = (float*)d_out;

    k_qproj <<<dim3(8, 8, 4),  128>>>(query, wq, out);
    k_uproj <<<dim3(8, HH),    128>>>(wk);
    k_scores<<<dim3(16, BB),   64>>>(key);
    k_wpart <<<dim3(2, 8, BB), 128>>>(value);   // profiled slot #4
    k_oproj <<<dim3(8, 8, 8),  128>>>(wv, out);
}

// round 14
// speedup vs baseline: 1.1161x; 1.0413x over previous
#include <cuda_runtime.h>

#define BB 32
#define NN 4096
#define DD 1024
#define HH 16

// Scratch (device globals)
__device__ float  g_qp[8][BB * DD];          // q projection partials over 8 d-ranges
__device__ float  g_Ut[BB * DD * HH];        // folded key vectors, transposed [b][d][h] (scaled 1/8)
__device__ float  g_att[BB * HH * NN];       // RAW scores
__device__ float2 g_stat[BB * HH * 32];      // per-(b,h,128n-tile) (max, sumexp)
__device__ float  g_wp[8][BB * HH * DD];     // normalized attn@value partials over 8 n-segments

typedef unsigned long long u64;

__device__ __forceinline__ void fma2(u64 &d, u64 a, u64 b) {
    asm("fma.rn.f32x2 %0, %1, %2, %0;" : "+l"(d) : "l"(a), "l"(b));
}
__device__ __forceinline__ u64 pack2(float lo, float hi) {
    u64 r; asm("mov.b64 %0, {%1, %2};" : "=l"(r) : "f"(lo), "f"(hi)); return r;
}
__device__ __forceinline__ void unpack2(u64 v, float &lo, float &hi) {
    asm("mov.b64 {%0, %1}, %2;" : "=f"(lo), "=f"(hi) : "l"(v));
}
__device__ __forceinline__ unsigned smem_u32(const void* p) {
    return (unsigned)__cvta_generic_to_shared(p);
}
__device__ __forceinline__ void cpasync16(unsigned dst, const void* src) {
    asm volatile("cp.async.cg.shared.global [%0], [%1], 16;\n" :: "r"(dst), "l"(src));
}
#define CP_COMMIT() asm volatile("cp.async.commit_group;\n" ::: "memory")
#define CP_WAIT(n)  asm volatile("cp.async.wait_group %0;\n" :: "n"(n) : "memory")

// ---------------------------------------------------------------------------
// Kernel A: qp[dsp][b,c] = sum_{d in dsp-range(128)} query[b,d] * wq[d,c]
// d-split 8: grid (8 c-tiles, 8 b-groups, 8 d-splits) = 512 blocks.
// Also zeroes d_out (first 256 blocks cover 32768 floats).
// ---------------------------------------------------------------------------
__global__ __launch_bounds__(128) void k_qproj(const float* __restrict__ query,
                                               const float* __restrict__ wq,
                                               float* __restrict__ out) {
    const int tx  = threadIdx.x;
    const int c0  = blockIdx.x * 128;
    const int b0  = blockIdx.y * 4;
    const int dsp = blockIdx.z;
    const int dr0 = dsp * 128;

    {
        int lin = blockIdx.x + 8 * blockIdx.y + 64 * blockIdx.z;
        if (lin < 256) out[lin * 128 + tx] = 0.0f;
    }

    __shared__ __align__(16) float sq[4][128];
    {
        int bb = tx >> 5, d4 = tx & 31;   // 128 float4 total, 1 per thread
        *(float4*)&sq[bb][d4 * 4] =
            *(const float4*)(query + (size_t)(b0 + bb) * DD + dr0 + d4 * 4);
    }
    __syncthreads();

    u64 acc[4] = {0ull, 0ull, 0ull, 0ull};
    const float* wc = wq + (size_t)dr0 * DD + c0 + tx;
#pragma unroll 16
    for (int d = 0; d < 128; d += 2) {
        float w0 = wc[(size_t)d * DD];
        float w1 = wc[(size_t)(d + 1) * DD];
        u64 w2 = pack2(w0, w1);
#pragma unroll
        for (int bb = 0; bb < 4; bb++) {
            u64 q2 = *(const u64*)&sq[bb][d];
            fma2(acc[bb], q2, w2);
        }
    }
#pragma unroll
    for (int bb = 0; bb < 4; bb++) {
        float lo, hi; unpack2(acc[bb], lo, hi);
        g_qp[dsp][(size_t)(b0 + bb) * DD + c0 + tx] = lo + hi;
    }
}

// ---------------------------------------------------------------------------
// Kernel B: Ut[b,d,h] = (1/8) * sum_{c<64} wk[d, h*64+c] * q[b, h*64+c]
// b-split 4: grid (8 d-tiles, 16 h, 4 b-groups) = 512 blocks; 8 b per block.
// wk tile re-read x4 (L2-resident). q partials (8) summed during staging.
// ---------------------------------------------------------------------------
__global__ __launch_bounds__(128) void k_uproj(const float* __restrict__ wk) {
    const int tx = threadIdx.x;
    const int d0 = blockIdx.x * 128;
    const int h  = blockIdx.y;
    const int bg = blockIdx.z * 8;
    __shared__ __align__(16) float4 swk4[128 * 17];
    __shared__ __align__(16) float  sq[8][64];

#pragma unroll
    for (int i = 0; i < 16; i++) {
        int fl = i * 128 + tx;
        int r  = fl >> 4, c4 = fl & 15;
        swk4[r * 17 + c4] =
            *(const float4*)(wk + (size_t)(d0 + r) * DD + h * 64 + c4 * 4);
    }
    {
        int bb = tx >> 4, c4 = tx & 15;   // 128 float4 total, 1 per thread
        size_t gidx = (size_t)(bg + bb) * DD + h * 64 + c4 * 4;
        float4 s = *(const float4*)(g_qp[0] + gidx);
#pragma unroll
        for (int p = 1; p < 8; p++) {
            float4 a = *(const float4*)(g_qp[p] + gidx);
            s.x += a.x; s.y += a.y; s.z += a.z; s.w += a.w;
        }
        *(float4*)&sq[bb][c4 * 4] = s;
    }
    __syncthreads();

    ulonglong2 wreg[16];
#pragma unroll
    for (int c4 = 0; c4 < 16; c4++)
        wreg[c4] = *(const ulonglong2*)&swk4[tx * 17 + c4];

    const int dst_base = (d0 + tx) * HH + h;
#pragma unroll 2
    for (int bb = 0; bb < 8; bb++) {
        u64 a2 = 0ull;
#pragma unroll
        for (int c4 = 0; c4 < 16; c4++) {
            ulonglong2 q2 = *(const ulonglong2*)&sq[bb][c4 * 4];
            fma2(a2, wreg[c4].x, q2.x);
            fma2(a2, wreg[c4].y, q2.y);
        }
        float lo, hi; unpack2(a2, lo, hi);
        g_Ut[(size_t)(bg + bb) * (DD * HH) + dst_base] = (lo + hi) * 0.125f;
    }
}

// ---------------------------------------------------------------------------
// Kernel C: raw scores + per-warp-tile softmax stats. (proven, frozen)
// ---------------------------------------------------------------------------
__global__ __launch_bounds__(64, 5) void k_scores(const float* __restrict__ key) {
    const int tx   = threadIdx.x;
    const int w    = tx >> 5;
    const int l    = tx & 31;
    const int b    = blockIdx.y;
    const int n0   = blockIdx.x * 256;
    const int nwrp = n0 + w * 128;

    __shared__ __align__(16) float4 skW[2][2][128 * 5];
    __shared__ __align__(16) float4 sUW[2][2][64];

    const float* keyw = key + ((size_t)b * NN + nwrp) * DD;
    const float* Utb  = g_Ut + (size_t)b * (DD * HH);

    u64 acc[4][8];
#pragma unroll
    for (int n4 = 0; n4 < 4; n4++)
#pragma unroll
        for (int p = 0; p < 8; p++) acc[n4][p] = 0ull;

    {
#pragma unroll
        for (int i = 0; i < 16; i++) {
            int fl = i * 32 + l;
            int n = fl >> 2, q4 = fl & 3;
            cpasync16(smem_u32(&skW[w][0][n * 5 + q4]),
                      keyw + (size_t)n * DD + q4 * 4);
        }
#pragma unroll
        for (int j = 0; j < 2; j++)
            cpasync16(smem_u32(&sUW[w][0][j * 32 + l]), Utb + (j * 32 + l) * 4);
        CP_COMMIT();
    }

#pragma unroll 1
    for (int ch = 0; ch < 64; ch++) {
        if (ch + 1 < 64) {
            const int st = (ch + 1) & 1, d0 = (ch + 1) * 16;
#pragma unroll
            for (int i = 0; i < 16; i++) {
                int fl = i * 32 + l;
                int n = fl >> 2, q4 = fl & 3;
                cpasync16(smem_u32(&skW[w][st][n * 5 + q4]),
                          keyw + (size_t)n * DD + d0 + q4 * 4);
            }
#pragma unroll
            for (int j = 0; j < 2; j++)
                cpasync16(smem_u32(&sUW[w][st][j * 32 + l]),
                          Utb + d0 * HH + (j * 32 + l) * 4);
            CP_COMMIT();
            CP_WAIT(1);
        } else {
            CP_WAIT(0);
        }
        __syncwarp();

        const int st = ch & 1;
#pragma unroll
        for (int g = 0; g < 4; g++) {
            float4 kv[4];
#pragma unroll
            for (int n4 = 0; n4 < 4; n4++)
                kv[n4] = skW[w][st][(n4 * 32 + l) * 5 + g];
#pragma unroll
            for (int s = 0; s < 4; s++) {
                int dd = g * 4 + s;
                const ulonglong2* uv = (const ulonglong2*)&sUW[w][st][dd * 4];
                ulonglong2 u0 = uv[0], u1 = uv[1];
                ulonglong2 u2 = uv[2], u3 = uv[3];
#pragma unroll
                for (int n4 = 0; n4 < 4; n4++) {
                    float kvs = (s == 0) ? kv[n4].x : (s == 1) ? kv[n4].y
                              : (s == 2) ? kv[n4].z : kv[n4].w;
                    u64 kv2 = pack2(kvs, kvs);
                    fma2(acc[n4][0], u0.x, kv2);
                    fma2(acc[n4][1], u0.y, kv2);
                    fma2(acc[n4][2], u1.x, kv2);
                    fma2(acc[n4][3], u1.y, kv2);
                    fma2(acc[n4][4], u2.x, kv2);
                    fma2(acc[n4][5], u2.y, kv2);
                    fma2(acc[n4][6], u3.x, kv2);
                    fma2(acc[n4][7], u3.y, kv2);
                }
            }
        }
        __syncwarp();
    }

#pragma unroll
    for (int n4 = 0; n4 < 4; n4++) {
#pragma unroll
        for (int p = 0; p < 8; p++) {
            float lo, hi;
            unpack2(acc[n4][p], lo, hi);
            g_att[((size_t)b * HH + 2 * p)     * NN + nwrp + n4 * 32 + l] = lo;
            g_att[((size_t)b * HH + 2 * p + 1) * NN + nwrp + n4 * 32 + l] = hi;
        }
    }

    float mt[16];
#pragma unroll
    for (int h = 0; h < 16; h++) mt[h] = -3e38f;
#pragma unroll
    for (int n4 = 0; n4 < 4; n4++)
#pragma unroll
        for (int p = 0; p < 8; p++) {
            float lo, hi; unpack2(acc[n4][p], lo, hi);
            mt[2 * p]     = fmaxf(mt[2 * p], lo);
            mt[2 * p + 1] = fmaxf(mt[2 * p + 1], hi);
        }
#pragma unroll
    for (int h = 0; h < 16; h++)
#pragma unroll
        for (int o = 16; o; o >>= 1)
            mt[h] = fmaxf(mt[h], __shfl_xor_sync(0xffffffffu, mt[h], o));

    float st[16];
#pragma unroll
    for (int h = 0; h < 16; h++) st[h] = 0.f;
#pragma unroll
    for (int n4 = 0; n4 < 4; n4++)
#pragma unroll
        for (int p = 0; p < 8; p++) {
            float lo, hi; unpack2(acc[n4][p], lo, hi);
            st[2 * p]     += __expf(lo - mt[2 * p]);
            st[2 * p + 1] += __expf(hi - mt[2 * p + 1]);
        }
#pragma unroll
    for (int h = 0; h < 16; h++)
#pragma unroll
        for (int o = 16; o; o >>= 1)
            st[h] += __shfl_xor_sync(0xffffffffu, st[h], o);

    if (l == 0) {
        int wtile = blockIdx.x * 2 + w;
#pragma unroll
        for (int h = 0; h < 16; h++)
            g_stat[((size_t)b * HH + h) * 32 + wtile] = make_float2(mt[h], st[h]);
    }
}

// ---------------------------------------------------------------------------
// Kernel E: wp[seg][b,h,d] = sum_{n in seg(512)} attn[b,h,n]*value[b,n,d]
// (proven, frozen) Softmax applied during att staging from tile stats.
// ---------------------------------------------------------------------------
__global__ __launch_bounds__(128, 3) void k_wpart(const float* __restrict__ value) {
    const int tx  = threadIdx.x;
    const int d0  = blockIdx.x * 512;
    const int seg = blockIdx.y;
    const int b   = blockIdx.z;

    __shared__ __align__(16) float  sA[512 * 20];    // [n][16h + 4 pad], 40KB
    __shared__ __align__(16) float4 sV[2][8][128];   // 2 stages x 8n x 512d, 32KB
    __shared__ float2 sMS[16];                       // (m_glob, 1/s_glob) per head

    if (tx < 16) {
        const float2* gs = g_stat + ((size_t)b * HH + tx) * 32;
        float m = -3e38f;
#pragma unroll
        for (int t = 0; t < 32; t++) m = fmaxf(m, gs[t].x);
        float s = 0.f;
#pragma unroll
        for (int t = 0; t < 32; t++) {
            float2 p = gs[t];
            s += p.y * __expf(p.x - m);
        }
        sMS[tx] = make_float2(m, 1.f / s);
    }

    const float* valb = value + ((size_t)b * NN + seg * 512) * DD + d0 + tx * 4;

#pragma unroll
    for (int j = 0; j < 8; j++)
        cpasync16(smem_u32(&sV[0][j][tx]), valb + (size_t)j * DD);
    CP_COMMIT();

    __syncthreads();   // sMS ready

    const float* attb = g_att + (size_t)b * HH * NN + seg * 512;
#pragma unroll
    for (int i = 0; i < 16; i++) {
        int fl = i * 128 + tx;
        int h = fl >> 7, n4 = (fl & 127) * 4;
        float4 a = *(const float4*)(attb + (size_t)h * NN + n4);
        float2 ms = sMS[h];
        sA[(n4 + 0) * 20 + h] = __expf(a.x - ms.x) * ms.y;
        sA[(n4 + 1) * 20 + h] = __expf(a.y - ms.x) * ms.y;
        sA[(n4 + 2) * 20 + h] = __expf(a.z - ms.x) * ms.y;
        sA[(n4 + 3) * 20 + h] = __expf(a.w - ms.x) * ms.y;
    }
    __syncthreads();

    u64 acc[32];
#pragma unroll
    for (int p = 0; p < 32; p++) acc[p] = 0ull;

#pragma unroll 1
    for (int ch = 0; ch < 64; ch++) {
        if (ch + 1 < 64) {
            const int st = (ch + 1) & 1;
            const float* src = valb + (size_t)(ch + 1) * 8 * DD;
#pragma unroll
            for (int j = 0; j < 8; j++)
                cpasync16(smem_u32(&sV[st][j][tx]), src + (size_t)j * DD);
            CP_COMMIT();
            CP_WAIT(1);
        } else {
            CP_WAIT(0);
        }
        // no barrier: this thread reads only the words it copied itself

        const int st = ch & 1;
        const float* sArow = &sA[ch * 8 * 20];
#pragma unroll
        for (int j = 0; j < 8; j++) {
            float4 v4 = sV[st][j][tx];
            float vs[4] = {v4.x, v4.y, v4.z, v4.w};
            const ulonglong2* av = (const ulonglong2*)(sArow + j * 20);
            ulonglong2 a0 = av[0], a1 = av[1], a2 = av[2], a3 = av[3];
#pragma unroll
            for (int dd = 0; dd < 4; dd++) {
                u64 v2 = pack2(vs[dd], vs[dd]);
                fma2(acc[dd * 8 + 0], a0.x, v2);
                fma2(acc[dd * 8 + 1], a0.y, v2);
                fma2(acc[dd * 8 + 2], a1.x, v2);
                fma2(acc[dd * 8 + 3], a1.y, v2);
                fma2(acc[dd * 8 + 4], a2.x, v2);
                fma2(acc[dd * 8 + 5], a2.y, v2);
                fma2(acc[dd * 8 + 6], a3.x, v2);
                fma2(acc[dd * 8 + 7], a3.y, v2);
            }
        }
    }

#pragma unroll
    for (int hp = 0; hp < 8; hp++) {
        float l0, h0x, l1, h1x, l2, h2x, l3, h3x;
        unpack2(acc[0 * 8 + hp], l0, h0x);
        unpack2(acc[1 * 8 + hp], l1, h1x);
        unpack2(acc[2 * 8 + hp], l2, h2x);
        unpack2(acc[3 * 8 + hp], l3, h3x);
        float4 olo = make_float4(l0, l1, l2, l3);
        float4 ohi = make_float4(h0x, h1x, h2x, h3x);
        *(float4*)(g_wp[seg] + ((size_t)b * HH + 2 * hp)     * DD + d0 + tx * 4) = olo;
        *(float4*)(g_wp[seg] + ((size_t)b * HH + 2 * hp + 1) * DD + d0 + tx * 4) = ohi;
    }
}

// ---------------------------------------------------------------------------
// Kernel F: out[b,c] += sum_{d in dsp-range(128)} w[b, c>>6, d] * wv[d, c]
// (R13 proven: d-split 8, 512 blocks)
// ---------------------------------------------------------------------------
__global__ __launch_bounds__(128) void k_oproj(const float* __restrict__ wv,
                                               float* __restrict__ out) {
    const int tx  = threadIdx.x;
    const int c0  = blockIdx.x * 128;
    const int b0  = blockIdx.y * 4;
    const int dsp = blockIdx.z;
    const int dr0 = dsp * 128;
    const int h0  = c0 >> 6;
    __shared__ __align__(16) float sw[4][2][128];

#pragma unroll
    for (int i = 0; i < 2; i++) {
        int fl = i * 128 + tx;                 // 256 float4 total
        int bb = fl >> 6, hh = (fl >> 5) & 1, d4 = fl & 31;
        size_t gidx = ((size_t)(b0 + bb) * HH + h0 + hh) * DD + dr0 + d4 * 4;
        float4 s = *(const float4*)(g_wp[0] + gidx);
#pragma unroll
        for (int p = 1; p < 8; p++) {
            float4 a = *(const float4*)(g_wp[p] + gidx);
            s.x += a.x; s.y += a.y; s.z += a.z; s.w += a.w;
        }
        *(float4*)&sw[bb][hh][d4 * 4] = s;
    }
    __syncthreads();

    const int hin = tx >> 6;
    u64 acc[4] = {0ull, 0ull, 0ull, 0ull};
    const float* wc = wv + (size_t)dr0 * DD + c0 + tx;
#pragma unroll 16
    for (int dd = 0; dd < 128; dd += 2) {
        float w0 = wc[(size_t)dd * DD];
        float w1 = wc[(size_t)(dd + 1) * DD];
        u64 w2 = pack2(w0, w1);
#pragma unroll
        for (int bb = 0; bb < 4; bb++) {
            u64 s2 = *(const u64*)&sw[bb][hin][dd];
            fma2(acc[bb], s2, w2);
        }
    }
#pragma unroll
    for (int bb = 0; bb < 4; bb++) {
        float lo, hi; unpack2(acc[bb], lo, hi);
        atomicAdd(&out[(size_t)(b0 + bb) * DD + c0 + tx], lo + hi);
    }
}

// ---------------------------------------------------------------------------
extern "C" void kernel_launch(void* const* d_in, const int* in_sizes, int n_in,
                              void* d_out, int out_size) {
    const float* query = (const float*)d_in[0];
    const float* key   = (const float*)d_in[1];
    const float* value = (const float*)d_in[2];
    const float* wq    = (const float*)d_in[3];
    const float* wk    = (const float*)d_in[4];
    const float* wv    = (const float*)d_in[5];
    float* out = (float*)d_out;

    k_qproj <<<dim3(8, 8, 8),   128>>>(query, wq, out);
    k_uproj <<<dim3(8, HH, 4),  128>>>(wk);
    k_scores<<<dim3(16, BB),    64>>>(key);
    k_wpart <<<dim3(2, 8, BB),  128>>>(value);   // profiled slot #4
    k_oproj <<<dim3(8, 8, 8),   128>>>(wv, out);
}

// round 15
// speedup vs baseline: 1.2598x; 1.1287x over previous
#include <cuda_runtime.h>

#define BB 32
#define NN 4096
#define DD 1024
#define HH 16

// Scratch (device globals)
__device__ float  g_qp[8][BB * DD];          // q projection partials over 8 d-ranges
__device__ float  g_Ut[BB * DD * HH];        // folded key vectors, transposed [b][d][h] (scaled 1/8)
__device__ float  g_att[BB * HH * NN];       // RAW scores
__device__ float2 g_stat[BB * HH * 32];      // per-(b,h,128n-tile) (max, sumexp)
__device__ float  g_wp[8][BB * HH * DD];     // normalized attn@value partials over 8 n-segments

typedef unsigned long long u64;

__device__ __forceinline__ void fma2(u64 &d, u64 a, u64 b) {
    asm("fma.rn.f32x2 %0, %1, %2, %0;" : "+l"(d) : "l"(a), "l"(b));
}
__device__ __forceinline__ u64 pack2(float lo, float hi) {
    u64 r; asm("mov.b64 %0, {%1, %2};" : "=l"(r) : "f"(lo), "f"(hi)); return r;
}
__device__ __forceinline__ void unpack2(u64 v, float &lo, float &hi) {
    asm("mov.b64 {%0, %1}, %2;" : "=f"(lo), "=f"(hi) : "l"(v));
}
__device__ __forceinline__ unsigned smem_u32(const void* p) {
    return (unsigned)__cvta_generic_to_shared(p);
}
__device__ __forceinline__ void cpasync16(unsigned dst, const void* src) {
    asm volatile("cp.async.cg.shared.global [%0], [%1], 16;\n" :: "r"(dst), "l"(src));
}
#define CP_COMMIT() asm volatile("cp.async.commit_group;\n" ::: "memory")
#define CP_WAIT(n)  asm volatile("cp.async.wait_group %0;\n" :: "n"(n) : "memory")

// ---------------------------------------------------------------------------
// Kernel A: qp[dsp][b,c] = sum_{d in dsp-range(128)} query[b,d] * wq[d,c]
// d-split 8: 512 blocks. Also zeroes d_out (first 256 blocks).
// ---------------------------------------------------------------------------
__global__ __launch_bounds__(128) void k_qproj(const float* __restrict__ query,
                                               const float* __restrict__ wq,
                                               float* __restrict__ out) {
    const int tx  = threadIdx.x;
    const int c0  = blockIdx.x * 128;
    const int b0  = blockIdx.y * 4;
    const int dsp = blockIdx.z;
    const int dr0 = dsp * 128;

    {
        int lin = blockIdx.x + 8 * blockIdx.y + 64 * blockIdx.z;
        if (lin < 256) out[lin * 128 + tx] = 0.0f;
    }

    __shared__ __align__(16) float sq[4][128];
    {
        int bb = tx >> 5, d4 = tx & 31;
        *(float4*)&sq[bb][d4 * 4] =
            *(const float4*)(query + (size_t)(b0 + bb) * DD + dr0 + d4 * 4);
    }
    __syncthreads();

    u64 acc[4] = {0ull, 0ull, 0ull, 0ull};
    const float* wc = wq + (size_t)dr0 * DD + c0 + tx;
#pragma unroll 16
    for (int d = 0; d < 128; d += 2) {
        float w0 = wc[(size_t)d * DD];
        float w1 = wc[(size_t)(d + 1) * DD];
        u64 w2 = pack2(w0, w1);
#pragma unroll
        for (int bb = 0; bb < 4; bb++) {
            u64 q2 = *(const u64*)&sq[bb][d];
            fma2(acc[bb], q2, w2);
        }
    }
#pragma unroll
    for (int bb = 0; bb < 4; bb++) {
        float lo, hi; unpack2(acc[bb], lo, hi);
        g_qp[dsp][(size_t)(b0 + bb) * DD + c0 + tx] = lo + hi;
    }
}

// ---------------------------------------------------------------------------
// Kernel B: Ut[b,d,h] = (1/8) * sum_{c<64} wk[d, h*64+c] * q[b, h*64+c]
// b-split 4: 512 blocks; 8 b per block. q partials (8) summed during staging.
// ---------------------------------------------------------------------------
__global__ __launch_bounds__(128) void k_uproj(const float* __restrict__ wk) {
    const int tx = threadIdx.x;
    const int d0 = blockIdx.x * 128;
    const int h  = blockIdx.y;
    const int bg = blockIdx.z * 8;
    __shared__ __align__(16) float4 swk4[128 * 17];
    __shared__ __align__(16) float  sq[8][64];

#pragma unroll
    for (int i = 0; i < 16; i++) {
        int fl = i * 128 + tx;
        int r  = fl >> 4, c4 = fl & 15;
        swk4[r * 17 + c4] =
            *(const float4*)(wk + (size_t)(d0 + r) * DD + h * 64 + c4 * 4);
    }
    {
        int bb = tx >> 4, c4 = tx & 15;
        size_t gidx = (size_t)(bg + bb) * DD + h * 64 + c4 * 4;
        float4 s = *(const float4*)(g_qp[0] + gidx);
#pragma unroll
        for (int p = 1; p < 8; p++) {
            float4 a = *(const float4*)(g_qp[p] + gidx);
            s.x += a.x; s.y += a.y; s.z += a.z; s.w += a.w;
        }
        *(float4*)&sq[bb][c4 * 4] = s;
    }
    __syncthreads();

    ulonglong2 wreg[16];
#pragma unroll
    for (int c4 = 0; c4 < 16; c4++)
        wreg[c4] = *(const ulonglong2*)&swk4[tx * 17 + c4];

    const int dst_base = (d0 + tx) * HH + h;
#pragma unroll 2
    for (int bb = 0; bb < 8; bb++) {
        u64 a2 = 0ull;
#pragma unroll
        for (int c4 = 0; c4 < 16; c4++) {
            ulonglong2 q2 = *(const ulonglong2*)&sq[bb][c4 * 4];
            fma2(a2, wreg[c4].x, q2.x);
            fma2(a2, wreg[c4].y, q2.y);
        }
        float lo, hi; unpack2(a2, lo, hi);
        g_Ut[(size_t)(bg + bb) * (DD * HH) + dst_base] = (lo + hi) * 0.125f;
    }
}

// ---------------------------------------------------------------------------
// Kernel C: raw scores + per-warp-tile softmax stats. (proven, frozen;
// b-offset arg for the two-stream half-batch split)
// ---------------------------------------------------------------------------
__global__ __launch_bounds__(64, 5) void k_scores(const float* __restrict__ key,
                                                  int boff) {
    const int tx   = threadIdx.x;
    const int w    = tx >> 5;
    const int l    = tx & 31;
    const int b    = blockIdx.y + boff;
    const int n0   = blockIdx.x * 256;
    const int nwrp = n0 + w * 128;

    __shared__ __align__(16) float4 skW[2][2][128 * 5];
    __shared__ __align__(16) float4 sUW[2][2][64];

    const float* keyw = key + ((size_t)b * NN + nwrp) * DD;
    const float* Utb  = g_Ut + (size_t)b * (DD * HH);

    u64 acc[4][8];
#pragma unroll
    for (int n4 = 0; n4 < 4; n4++)
#pragma unroll
        for (int p = 0; p < 8; p++) acc[n4][p] = 0ull;

    {
#pragma unroll
        for (int i = 0; i < 16; i++) {
            int fl = i * 32 + l;
            int n = fl >> 2, q4 = fl & 3;
            cpasync16(smem_u32(&skW[w][0][n * 5 + q4]),
                      keyw + (size_t)n * DD + q4 * 4);
        }
#pragma unroll
        for (int j = 0; j < 2; j++)
            cpasync16(smem_u32(&sUW[w][0][j * 32 + l]), Utb + (j * 32 + l) * 4);
        CP_COMMIT();
    }

#pragma unroll 1
    for (int ch = 0; ch < 64; ch++) {
        if (ch + 1 < 64) {
            const int st = (ch + 1) & 1, d0 = (ch + 1) * 16;
#pragma unroll
            for (int i = 0; i < 16; i++) {
                int fl = i * 32 + l;
                int n = fl >> 2, q4 = fl & 3;
                cpasync16(smem_u32(&skW[w][st][n * 5 + q4]),
                          keyw + (size_t)n * DD + d0 + q4 * 4);
            }
#pragma unroll
            for (int j = 0; j < 2; j++)
                cpasync16(smem_u32(&sUW[w][st][j * 32 + l]),
                          Utb + d0 * HH + (j * 32 + l) * 4);
            CP_COMMIT();
            CP_WAIT(1);
        } else {
            CP_WAIT(0);
        }
        __syncwarp();

        const int st = ch & 1;
#pragma unroll
        for (int g = 0; g < 4; g++) {
            float4 kv[4];
#pragma unroll
            for (int n4 = 0; n4 < 4; n4++)
                kv[n4] = skW[w][st][(n4 * 32 + l) * 5 + g];
#pragma unroll
            for (int s = 0; s < 4; s++) {
                int dd = g * 4 + s;
                const ulonglong2* uv = (const ulonglong2*)&sUW[w][st][dd * 4];
                ulonglong2 u0 = uv[0], u1 = uv[1];
                ulonglong2 u2 = uv[2], u3 = uv[3];
#pragma unroll
                for (int n4 = 0; n4 < 4; n4++) {
                    float kvs = (s == 0) ? kv[n4].x : (s == 1) ? kv[n4].y
                              : (s == 2) ? kv[n4].z : kv[n4].w;
                    u64 kv2 = pack2(kvs, kvs);
                    fma2(acc[n4][0], u0.x, kv2);
                    fma2(acc[n4][1], u0.y, kv2);
                    fma2(acc[n4][2], u1.x, kv2);
                    fma2(acc[n4][3], u1.y, kv2);
                    fma2(acc[n4][4], u2.x, kv2);
                    fma2(acc[n4][5], u2.y, kv2);
                    fma2(acc[n4][6], u3.x, kv2);
                    fma2(acc[n4][7], u3.y, kv2);
                }
            }
        }
        __syncwarp();
    }

#pragma unroll
    for (int n4 = 0; n4 < 4; n4++) {
#pragma unroll
        for (int p = 0; p < 8; p++) {
            float lo, hi;
            unpack2(acc[n4][p], lo, hi);
            g_att[((size_t)b * HH + 2 * p)     * NN + nwrp + n4 * 32 + l] = lo;
            g_att[((size_t)b * HH + 2 * p + 1) * NN + nwrp + n4 * 32 + l] = hi;
        }
    }

    float mt[16];
#pragma unroll
    for (int h = 0; h < 16; h++) mt[h] = -3e38f;
#pragma unroll
    for (int n4 = 0; n4 < 4; n4++)
#pragma unroll
        for (int p = 0; p < 8; p++) {
            float lo, hi; unpack2(acc[n4][p], lo, hi);
            mt[2 * p]     = fmaxf(mt[2 * p], lo);
            mt[2 * p + 1] = fmaxf(mt[2 * p + 1], hi);
        }
#pragma unroll
    for (int h = 0; h < 16; h++)
#pragma unroll
        for (int o = 16; o; o >>= 1)
            mt[h] = fmaxf(mt[h], __shfl_xor_sync(0xffffffffu, mt[h], o));

    float st[16];
#pragma unroll
    for (int h = 0; h < 16; h++) st[h] = 0.f;
#pragma unroll
    for (int n4 = 0; n4 < 4; n4++)
#pragma unroll
        for (int p = 0; p < 8; p++) {
            float lo, hi; unpack2(acc[n4][p], lo, hi);
            st[2 * p]     += __expf(lo - mt[2 * p]);
            st[2 * p + 1] += __expf(hi - mt[2 * p + 1]);
        }
#pragma unroll
    for (int h = 0; h < 16; h++)
#pragma unroll
        for (int o = 16; o; o >>= 1)
            st[h] += __shfl_xor_sync(0xffffffffu, st[h], o);

    if (l == 0) {
        int wtile = blockIdx.x * 2 + w;
#pragma unroll
        for (int h = 0; h < 16; h++)
            g_stat[((size_t)b * HH + h) * 32 + wtile] = make_float2(mt[h], st[h]);
    }
}

// ---------------------------------------------------------------------------
// Kernel E: wp[seg][b,h,d] = sum_{n in seg(512)} attn[b,h,n]*value[b,n,d]
// (proven, frozen; b-offset arg) Softmax applied during att staging.
// ---------------------------------------------------------------------------
__global__ __launch_bounds__(128, 3) void k_wpart(const float* __restrict__ value,
                                                  int boff) {
    const int tx  = threadIdx.x;
    const int d0  = blockIdx.x * 512;
    const int seg = blockIdx.y;
    const int b   = blockIdx.z + boff;

    __shared__ __align__(16) float  sA[512 * 20];    // 40KB
    __shared__ __align__(16) float4 sV[2][8][128];   // 32KB
    __shared__ float2 sMS[16];

    if (tx < 16) {
        const float2* gs = g_stat + ((size_t)b * HH + tx) * 32;
        float m = -3e38f;
#pragma unroll
        for (int t = 0; t < 32; t++) m = fmaxf(m, gs[t].x);
        float s = 0.f;
#pragma unroll
        for (int t = 0; t < 32; t++) {
            float2 p = gs[t];
            s += p.y * __expf(p.x - m);
        }
        sMS[tx] = make_float2(m, 1.f / s);
    }

    const float* valb = value + ((size_t)b * NN + seg * 512) * DD + d0 + tx * 4;

#pragma unroll
    for (int j = 0; j < 8; j++)
        cpasync16(smem_u32(&sV[0][j][tx]), valb + (size_t)j * DD);
    CP_COMMIT();

    __syncthreads();   // sMS ready

    const float* attb = g_att + (size_t)b * HH * NN + seg * 512;
#pragma unroll
    for (int i = 0; i < 16; i++) {
        int fl = i * 128 + tx;
        int h = fl >> 7, n4 = (fl & 127) * 4;
        float4 a = *(const float4*)(attb + (size_t)h * NN + n4);
        float2 ms = sMS[h];
        sA[(n4 + 0) * 20 + h] = __expf(a.x - ms.x) * ms.y;
        sA[(n4 + 1) * 20 + h] = __expf(a.y - ms.x) * ms.y;
        sA[(n4 + 2) * 20 + h] = __expf(a.z - ms.x) * ms.y;
        sA[(n4 + 3) * 20 + h] = __expf(a.w - ms.x) * ms.y;
    }
    __syncthreads();

    u64 acc[32];
#pragma unroll
    for (int p = 0; p < 32; p++) acc[p] = 0ull;

#pragma unroll 1
    for (int ch = 0; ch < 64; ch++) {
        if (ch + 1 < 64) {
            const int st = (ch + 1) & 1;
            const float* src = valb + (size_t)(ch + 1) * 8 * DD;
#pragma unroll
            for (int j = 0; j < 8; j++)
                cpasync16(smem_u32(&sV[st][j][tx]), src + (size_t)j * DD);
            CP_COMMIT();
            CP_WAIT(1);
        } else {
            CP_WAIT(0);
        }
        // no barrier: this thread reads only the words it copied itself

        const int st = ch & 1;
        const float* sArow = &sA[ch * 8 * 20];
#pragma unroll
        for (int j = 0; j < 8; j++) {
            float4 v4 = sV[st][j][tx];
            float vs[4] = {v4.x, v4.y, v4.z, v4.w};
            const ulonglong2* av = (const ulonglong2*)(sArow + j * 20);
            ulonglong2 a0 = av[0], a1 = av[1], a2 = av[2], a3 = av[3];
#pragma unroll
            for (int dd = 0; dd < 4; dd++) {
                u64 v2 = pack2(vs[dd], vs[dd]);
                fma2(acc[dd * 8 + 0], a0.x, v2);
                fma2(acc[dd * 8 + 1], a0.y, v2);
                fma2(acc[dd * 8 + 2], a1.x, v2);
                fma2(acc[dd * 8 + 3], a1.y, v2);
                fma2(acc[dd * 8 + 4], a2.x, v2);
                fma2(acc[dd * 8 + 5], a2.y, v2);
                fma2(acc[dd * 8 + 6], a3.x, v2);
                fma2(acc[dd * 8 + 7], a3.y, v2);
            }
        }
    }

#pragma unroll
    for (int hp = 0; hp < 8; hp++) {
        float l0, h0x, l1, h1x, l2, h2x, l3, h3x;
        unpack2(acc[0 * 8 + hp], l0, h0x);
        unpack2(acc[1 * 8 + hp], l1, h1x);
        unpack2(acc[2 * 8 + hp], l2, h2x);
        unpack2(acc[3 * 8 + hp], l3, h3x);
        float4 olo = make_float4(l0, l1, l2, l3);
        float4 ohi = make_float4(h0x, h1x, h2x, h3x);
        *(float4*)(g_wp[seg] + ((size_t)b * HH + 2 * hp)     * DD + d0 + tx * 4) = olo;
        *(float4*)(g_wp[seg] + ((size_t)b * HH + 2 * hp + 1) * DD + d0 + tx * 4) = ohi;
    }
}

// ---------------------------------------------------------------------------
// Kernel F: out[b,c] += sum_{d in dsp-range(128)} w[b, c>>6, d] * wv[d, c]
// (proven, frozen; b-group offset arg)
// ---------------------------------------------------------------------------
__global__ __launch_bounds__(128) void k_oproj(const float* __restrict__ wv,
                                               float* __restrict__ out,
                                               int bgoff) {
    const int tx  = threadIdx.x;
    const int c0  = blockIdx.x * 128;
    const int b0  = (blockIdx.y + bgoff) * 4;
    const int dsp = blockIdx.z;
    const int dr0 = dsp * 128;
    const int h0  = c0 >> 6;
    __shared__ __align__(16) float sw[4][2][128];

#pragma unroll
    for (int i = 0; i < 2; i++) {
        int fl = i * 128 + tx;
        int bb = fl >> 6, hh = (fl >> 5) & 1, d4 = fl & 31;
        size_t gidx = ((size_t)(b0 + bb) * HH + h0 + hh) * DD + dr0 + d4 * 4;
        float4 s = *(const float4*)(g_wp[0] + gidx);
#pragma unroll
        for (int p = 1; p < 8; p++) {
            float4 a = *(const float4*)(g_wp[p] + gidx);
            s.x += a.x; s.y += a.y; s.z += a.z; s.w += a.w;
        }
        *(float4*)&sw[bb][hh][d4 * 4] = s;
    }
    __syncthreads();

    const int hin = tx >> 6;
    u64 acc[4] = {0ull, 0ull, 0ull, 0ull};
    const float* wc = wv + (size_t)dr0 * DD + c0 + tx;
#pragma unroll 16
    for (int dd = 0; dd < 128; dd += 2) {
        float w0 = wc[(size_t)dd * DD];
        float w1 = wc[(size_t)(dd + 1) * DD];
        u64 w2 = pack2(w0, w1);
#pragma unroll
        for (int bb = 0; bb < 4; bb++) {
            u64 s2 = *(const u64*)&sw[bb][hin][dd];
            fma2(acc[bb], s2, w2);
        }
    }
#pragma unroll
    for (int bb = 0; bb < 4; bb++) {
        float lo, hi; unpack2(acc[bb], lo, hi);
        atomicAdd(&out[(size_t)(b0 + bb) * DD + c0 + tx], lo + hi);
    }
}

// ---------------------------------------------------------------------------
// Two-stream half-batch pipeline:
//   s0: qproj -> uproj -> [fork e0] -> scores(b16-31) -> wpart -> oproj
//   s1: [wait e0] scores(b0-15) -> wpart -> oproj -> [e1]
//   s0: [wait e1]
// All inter-half state (g_att/g_stat/g_wp/out rows) is b-partitioned: no
// cross-stream data dependencies. Streams/events are lazily created once;
// the per-call GPU work is identical on every call (graph-capture fork/join).
// ---------------------------------------------------------------------------
extern "C" void kernel_launch(void* const* d_in, const int* in_sizes, int n_in,
                              void* d_out, int out_size) {
    const float* query = (const float*)d_in[0];
    const float* key   = (const float*)d_in[1];
    const float* value = (const float*)d_in[2];
    const float* wq    = (const float*)d_in[3];
    const float* wk    = (const float*)d_in[4];
    const float* wv    = (const float*)d_in[5];
    float* out = (float*)d_out;

    static cudaStream_t s1 = nullptr;
    static cudaEvent_t  e0 = nullptr, e1 = nullptr;
    if (s1 == nullptr) {
        cudaStreamCreateWithFlags(&s1, cudaStreamNonBlocking);
        cudaEventCreateWithFlags(&e0, cudaEventDisableTiming);
        cudaEventCreateWithFlags(&e1, cudaEventDisableTiming);
    }

    k_qproj<<<dim3(8, 8, 8),  128>>>(query, wq, out);
    k_uproj<<<dim3(8, HH, 4), 128>>>(wk);

    cudaEventRecord(e0, 0);
    cudaStreamWaitEvent(s1, e0, 0);

    // stream s1: first half (b 0..15)
    k_scores<<<dim3(16, 16),   64,  0, s1>>>(key, 0);
    k_wpart <<<dim3(2, 8, 16), 128, 0, s1>>>(value, 0);
    k_oproj <<<dim3(8, 4, 8),  128, 0, s1>>>(wv, out, 0);
    cudaEventRecord(e1, s1);

    // stream 0: second half (b 16..31)
    k_scores<<<dim3(16, 16),   64>>>(key, 16);
    k_wpart <<<dim3(2, 8, 16), 128>>>(value, 16);
    k_oproj <<<dim3(8, 4, 8),  128>>>(wv, out, 4);

    cudaStreamWaitEvent(0, e1, 0);
}

// round 16
// speedup vs baseline: 1.2761x; 1.0129x over previous
#include <cuda_runtime.h>

#define BB 32
#define NN 4096
#define DD 1024
#define HH 16

// Scratch (device globals)
__device__ float  g_qp[8][BB * DD];          // q projection partials over 8 d-ranges
__device__ float  g_Ut[BB * DD * HH];        // folded key vectors, transposed [b][d][h] (scaled 1/8)
__device__ float  g_att[BB * HH * NN];       // RAW scores
__device__ float2 g_stat[BB * HH * 32];      // per-(b,h,128n-tile) (max, sumexp)
__device__ float  g_wp[8][BB * HH * DD];     // normalized attn@value partials over 8 n-segments

typedef unsigned long long u64;

__device__ __forceinline__ void fma2(u64 &d, u64 a, u64 b) {
    asm("fma.rn.f32x2 %0, %1, %2, %0;" : "+l"(d) : "l"(a), "l"(b));
}
__device__ __forceinline__ u64 pack2(float lo, float hi) {
    u64 r; asm("mov.b64 %0, {%1, %2};" : "=l"(r) : "f"(lo), "f"(hi)); return r;
}
__device__ __forceinline__ void unpack2(u64 v, float &lo, float &hi) {
    asm("mov.b64 {%0, %1}, %2;" : "=f"(lo), "=f"(hi) : "l"(v));
}
__device__ __forceinline__ unsigned smem_u32(const void* p) {
    return (unsigned)__cvta_generic_to_shared(p);
}
__device__ __forceinline__ void cpasync16(unsigned dst, const void* src) {
    asm volatile("cp.async.cg.shared.global [%0], [%1], 16;\n" :: "r"(dst), "l"(src));
}
#define CP_COMMIT() asm volatile("cp.async.commit_group;\n" ::: "memory")
#define CP_WAIT(n)  asm volatile("cp.async.wait_group %0;\n" :: "n"(n) : "memory")

// ---------------------------------------------------------------------------
// Kernel A: qp[dsp][b,c] = sum_{d in dsp-range(128)} query[b,d] * wq[d,c]
// d-split 8: 512 blocks. Also zeroes d_out (first 256 blocks).
// ---------------------------------------------------------------------------
__global__ __launch_bounds__(128) void k_qproj(const float* __restrict__ query,
                                               const float* __restrict__ wq,
                                               float* __restrict__ out) {
    const int tx  = threadIdx.x;
    const int c0  = blockIdx.x * 128;
    const int b0  = blockIdx.y * 4;
    const int dsp = blockIdx.z;
    const int dr0 = dsp * 128;

    {
        int lin = blockIdx.x + 8 * blockIdx.y + 64 * blockIdx.z;
        if (lin < 256) out[lin * 128 + tx] = 0.0f;
    }

    __shared__ __align__(16) float sq[4][128];
    {
        int bb = tx >> 5, d4 = tx & 31;
        *(float4*)&sq[bb][d4 * 4] =
            *(const float4*)(query + (size_t)(b0 + bb) * DD + dr0 + d4 * 4);
    }
    __syncthreads();

    u64 acc[4] = {0ull, 0ull, 0ull, 0ull};
    const float* wc = wq + (size_t)dr0 * DD + c0 + tx;
#pragma unroll 16
    for (int d = 0; d < 128; d += 2) {
        float w0 = wc[(size_t)d * DD];
        float w1 = wc[(size_t)(d + 1) * DD];
        u64 w2 = pack2(w0, w1);
#pragma unroll
        for (int bb = 0; bb < 4; bb++) {
            u64 q2 = *(const u64*)&sq[bb][d];
            fma2(acc[bb], q2, w2);
        }
    }
#pragma unroll
    for (int bb = 0; bb < 4; bb++) {
        float lo, hi; unpack2(acc[bb], lo, hi);
        g_qp[dsp][(size_t)(b0 + bb) * DD + c0 + tx] = lo + hi;
    }
}

// ---------------------------------------------------------------------------
// Kernel B: Ut[b,d,h] for 8 consecutive b (boff arg; one quarter-batch).
// grid (8 d-tiles, 16 h) = 128 blocks per quarter.
// ---------------------------------------------------------------------------
__global__ __launch_bounds__(128) void k_uproj(const float* __restrict__ wk,
                                               int boff) {
    const int tx = threadIdx.x;
    const int d0 = blockIdx.x * 128;
    const int h  = blockIdx.y;
    const int bg = boff;
    __shared__ __align__(16) float4 swk4[128 * 17];
    __shared__ __align__(16) float  sq[8][64];

#pragma unroll
    for (int i = 0; i < 16; i++) {
        int fl = i * 128 + tx;
        int r  = fl >> 4, c4 = fl & 15;
        swk4[r * 17 + c4] =
            *(const float4*)(wk + (size_t)(d0 + r) * DD + h * 64 + c4 * 4);
    }
    {
        int bb = tx >> 4, c4 = tx & 15;
        size_t gidx = (size_t)(bg + bb) * DD + h * 64 + c4 * 4;
        float4 s = *(const float4*)(g_qp[0] + gidx);
#pragma unroll
        for (int p = 1; p < 8; p++) {
            float4 a = *(const float4*)(g_qp[p] + gidx);
            s.x += a.x; s.y += a.y; s.z += a.z; s.w += a.w;
        }
        *(float4*)&sq[bb][c4 * 4] = s;
    }
    __syncthreads();

    ulonglong2 wreg[16];
#pragma unroll
    for (int c4 = 0; c4 < 16; c4++)
        wreg[c4] = *(const ulonglong2*)&swk4[tx * 17 + c4];

    const int dst_base = (d0 + tx) * HH + h;
#pragma unroll 2
    for (int bb = 0; bb < 8; bb++) {
        u64 a2 = 0ull;
#pragma unroll
        for (int c4 = 0; c4 < 16; c4++) {
            ulonglong2 q2 = *(const ulonglong2*)&sq[bb][c4 * 4];
            fma2(a2, wreg[c4].x, q2.x);
            fma2(a2, wreg[c4].y, q2.y);
        }
        float lo, hi; unpack2(a2, lo, hi);
        g_Ut[(size_t)(bg + bb) * (DD * HH) + dst_base] = (lo + hi) * 0.125f;
    }
}

// ---------------------------------------------------------------------------
// Kernel C: raw scores + per-warp-tile softmax stats. (proven, frozen)
// ---------------------------------------------------------------------------
__global__ __launch_bounds__(64, 5) void k_scores(const float* __restrict__ key,
                                                  int boff) {
    const int tx   = threadIdx.x;
    const int w    = tx >> 5;
    const int l    = tx & 31;
    const int b    = blockIdx.y + boff;
    const int n0   = blockIdx.x * 256;
    const int nwrp = n0 + w * 128;

    __shared__ __align__(16) float4 skW[2][2][128 * 5];
    __shared__ __align__(16) float4 sUW[2][2][64];

    const float* keyw = key + ((size_t)b * NN + nwrp) * DD;
    const float* Utb  = g_Ut + (size_t)b * (DD * HH);

    u64 acc[4][8];
#pragma unroll
    for (int n4 = 0; n4 < 4; n4++)
#pragma unroll
        for (int p = 0; p < 8; p++) acc[n4][p] = 0ull;

    {
#pragma unroll
        for (int i = 0; i < 16; i++) {
            int fl = i * 32 + l;
            int n = fl >> 2, q4 = fl & 3;
            cpasync16(smem_u32(&skW[w][0][n * 5 + q4]),
                      keyw + (size_t)n * DD + q4 * 4);
        }
#pragma unroll
        for (int j = 0; j < 2; j++)
            cpasync16(smem_u32(&sUW[w][0][j * 32 + l]), Utb + (j * 32 + l) * 4);
        CP_COMMIT();
    }

#pragma unroll 1
    for (int ch = 0; ch < 64; ch++) {
        if (ch + 1 < 64) {
            const int st = (ch + 1) & 1, d0 = (ch + 1) * 16;
#pragma unroll
            for (int i = 0; i < 16; i++) {
                int fl = i * 32 + l;
                int n = fl >> 2, q4 = fl & 3;
                cpasync16(smem_u32(&skW[w][st][n * 5 + q4]),
                          keyw + (size_t)n * DD + d0 + q4 * 4);
            }
#pragma unroll
            for (int j = 0; j < 2; j++)
                cpasync16(smem_u32(&sUW[w][st][j * 32 + l]),
                          Utb + d0 * HH + (j * 32 + l) * 4);
            CP_COMMIT();
            CP_WAIT(1);
        } else {
            CP_WAIT(0);
        }
        __syncwarp();

        const int st = ch & 1;
#pragma unroll
        for (int g = 0; g < 4; g++) {
            float4 kv[4];
#pragma unroll
            for (int n4 = 0; n4 < 4; n4++)
                kv[n4] = skW[w][st][(n4 * 32 + l) * 5 + g];
#pragma unroll
            for (int s = 0; s < 4; s++) {
                int dd = g * 4 + s;
                const ulonglong2* uv = (const ulonglong2*)&sUW[w][st][dd * 4];
                ulonglong2 u0 = uv[0], u1 = uv[1];
                ulonglong2 u2 = uv[2], u3 = uv[3];
#pragma unroll
                for (int n4 = 0; n4 < 4; n4++) {
                    float kvs = (s == 0) ? kv[n4].x : (s == 1) ? kv[n4].y
                              : (s == 2) ? kv[n4].z : kv[n4].w;
                    u64 kv2 = pack2(kvs, kvs);
                    fma2(acc[n4][0], u0.x, kv2);
                    fma2(acc[n4][1], u0.y, kv2);
                    fma2(acc[n4][2], u1.x, kv2);
                    fma2(acc[n4][3], u1.y, kv2);
                    fma2(acc[n4][4], u2.x, kv2);
                    fma2(acc[n4][5], u2.y, kv2);
                    fma2(acc[n4][6], u3.x, kv2);
                    fma2(acc[n4][7], u3.y, kv2);
                }
            }
        }
        __syncwarp();
    }

#pragma unroll
    for (int n4 = 0; n4 < 4; n4++) {
#pragma unroll
        for (int p = 0; p < 8; p++) {
            float lo, hi;
            unpack2(acc[n4][p], lo, hi);
            g_att[((size_t)b * HH + 2 * p)     * NN + nwrp + n4 * 32 + l] = lo;
            g_att[((size_t)b * HH + 2 * p + 1) * NN + nwrp + n4 * 32 + l] = hi;
        }
    }

    float mt[16];
#pragma unroll
    for (int h = 0; h < 16; h++) mt[h] = -3e38f;
#pragma unroll
    for (int n4 = 0; n4 < 4; n4++)
#pragma unroll
        for (int p = 0; p < 8; p++) {
            float lo, hi; unpack2(acc[n4][p], lo, hi);
            mt[2 * p]     = fmaxf(mt[2 * p], lo);
            mt[2 * p + 1] = fmaxf(mt[2 * p + 1], hi);
        }
#pragma unroll
    for (int h = 0; h < 16; h++)
#pragma unroll
        for (int o = 16; o; o >>= 1)
            mt[h] = fmaxf(mt[h], __shfl_xor_sync(0xffffffffu, mt[h], o));

    float st[16];
#pragma unroll
    for (int h = 0; h < 16; h++) st[h] = 0.f;
#pragma unroll
    for (int n4 = 0; n4 < 4; n4++)
#pragma unroll
        for (int p = 0; p < 8; p++) {
            float lo, hi; unpack2(acc[n4][p], lo, hi);
            st[2 * p]     += __expf(lo - mt[2 * p]);
            st[2 * p + 1] += __expf(hi - mt[2 * p + 1]);
        }
#pragma unroll
    for (int h = 0; h < 16; h++)
#pragma unroll
        for (int o = 16; o; o >>= 1)
            st[h] += __shfl_xor_sync(0xffffffffu, st[h], o);

    if (l == 0) {
        int wtile = blockIdx.x * 2 + w;
#pragma unroll
        for (int h = 0; h < 16; h++)
            g_stat[((size_t)b * HH + h) * 32 + wtile] = make_float2(mt[h], st[h]);
    }
}

// ---------------------------------------------------------------------------
// Kernel E: wp[seg][b,h,d] = sum_{n in seg(512)} attn[b,h,n]*value[b,n,d]
// (proven, frozen; boff arg) Softmax applied during att staging.
// ---------------------------------------------------------------------------
__global__ __launch_bounds__(128, 3) void k_wpart(const float* __restrict__ value,
                                                  int boff) {
    const int tx  = threadIdx.x;
    const int d0  = blockIdx.x * 512;
    const int seg = blockIdx.y;
    const int b   = blockIdx.z + boff;

    __shared__ __align__(16) float  sA[512 * 20];    // 40KB
    __shared__ __align__(16) float4 sV[2][8][128];   // 32KB
    __shared__ float2 sMS[16];

    if (tx < 16) {
        const float2* gs = g_stat + ((size_t)b * HH + tx) * 32;
        float m = -3e38f;
#pragma unroll
        for (int t = 0; t < 32; t++) m = fmaxf(m, gs[t].x);
        float s = 0.f;
#pragma unroll
        for (int t = 0; t < 32; t++) {
            float2 p = gs[t];
            s += p.y * __expf(p.x - m);
        }
        sMS[tx] = make_float2(m, 1.f / s);
    }

    const float* valb = value + ((size_t)b * NN + seg * 512) * DD + d0 + tx * 4;

#pragma unroll
    for (int j = 0; j < 8; j++)
        cpasync16(smem_u32(&sV[0][j][tx]), valb + (size_t)j * DD);
    CP_COMMIT();

    __syncthreads();   // sMS ready

    const float* attb = g_att + (size_t)b * HH * NN + seg * 512;
#pragma unroll
    for (int i = 0; i < 16; i++) {
        int fl = i * 128 + tx;
        int h = fl >> 7, n4 = (fl & 127) * 4;
        float4 a = *(const float4*)(attb + (size_t)h * NN + n4);
        float2 ms = sMS[h];
        sA[(n4 + 0) * 20 + h] = __expf(a.x - ms.x) * ms.y;
        sA[(n4 + 1) * 20 + h] = __expf(a.y - ms.x) * ms.y;
        sA[(n4 + 2) * 20 + h] = __expf(a.z - ms.x) * ms.y;
        sA[(n4 + 3) * 20 + h] = __expf(a.w - ms.x) * ms.y;
    }
    __syncthreads();

    u64 acc[32];
#pragma unroll
    for (int p = 0; p < 32; p++) acc[p] = 0ull;

#pragma unroll 1
    for (int ch = 0; ch < 64; ch++) {
        if (ch + 1 < 64) {
            const int st = (ch + 1) & 1;
            const float* src = valb + (size_t)(ch + 1) * 8 * DD;
#pragma unroll
            for (int j = 0; j < 8; j++)
                cpasync16(smem_u32(&sV[st][j][tx]), src + (size_t)j * DD);
            CP_COMMIT();
            CP_WAIT(1);
        } else {
            CP_WAIT(0);
        }
        // no barrier: this thread reads only the words it copied itself

        const int st = ch & 1;
        const float* sArow = &sA[ch * 8 * 20];
#pragma unroll
        for (int j = 0; j < 8; j++) {
            float4 v4 = sV[st][j][tx];
            float vs[4] = {v4.x, v4.y, v4.z, v4.w};
            const ulonglong2* av = (const ulonglong2*)(sArow + j * 20);
            ulonglong2 a0 = av[0], a1 = av[1], a2 = av[2], a3 = av[3];
#pragma unroll
            for (int dd = 0; dd < 4; dd++) {
                u64 v2 = pack2(vs[dd], vs[dd]);
                fma2(acc[dd * 8 + 0], a0.x, v2);
                fma2(acc[dd * 8 + 1], a0.y, v2);
                fma2(acc[dd * 8 + 2], a1.x, v2);
                fma2(acc[dd * 8 + 3], a1.y, v2);
                fma2(acc[dd * 8 + 4], a2.x, v2);
                fma2(acc[dd * 8 + 5], a2.y, v2);
                fma2(acc[dd * 8 + 6], a3.x, v2);
                fma2(acc[dd * 8 + 7], a3.y, v2);
            }
        }
    }

#pragma unroll
    for (int hp = 0; hp < 8; hp++) {
        float l0, h0x, l1, h1x, l2, h2x, l3, h3x;
        unpack2(acc[0 * 8 + hp], l0, h0x);
        unpack2(acc[1 * 8 + hp], l1, h1x);
        unpack2(acc[2 * 8 + hp], l2, h2x);
        unpack2(acc[3 * 8 + hp], l3, h3x);
        float4 olo = make_float4(l0, l1, l2, l3);
        float4 ohi = make_float4(h0x, h1x, h2x, h3x);
        *(float4*)(g_wp[seg] + ((size_t)b * HH + 2 * hp)     * DD + d0 + tx * 4) = olo;
        *(float4*)(g_wp[seg] + ((size_t)b * HH + 2 * hp + 1) * DD + d0 + tx * 4) = ohi;
    }
}

// ---------------------------------------------------------------------------
// Kernel F: out[b,c] += sum_{d in dsp-range(128)} w[b, c>>6, d] * wv[d, c]
// (proven, frozen; b-group offset arg)
// ---------------------------------------------------------------------------
__global__ __launch_bounds__(128) void k_oproj(const float* __restrict__ wv,
                                               float* __restrict__ out,
                                               int bgoff) {
    const int tx  = threadIdx.x;
    const int c0  = blockIdx.x * 128;
    const int b0  = (blockIdx.y + bgoff) * 4;
    const int dsp = blockIdx.z;
    const int dr0 = dsp * 128;
    const int h0  = c0 >> 6;
    __shared__ __align__(16) float sw[4][2][128];

#pragma unroll
    for (int i = 0; i < 2; i++) {
        int fl = i * 128 + tx;
        int bb = fl >> 6, hh = (fl >> 5) & 1, d4 = fl & 31;
        size_t gidx = ((size_t)(b0 + bb) * HH + h0 + hh) * DD + dr0 + d4 * 4;
        float4 s = *(const float4*)(g_wp[0] + gidx);
#pragma unroll
        for (int p = 1; p < 8; p++) {
            float4 a = *(const float4*)(g_wp[p] + gidx);
            s.x += a.x; s.y += a.y; s.z += a.z; s.w += a.w;
        }
        *(float4*)&sw[bb][hh][d4 * 4] = s;
    }
    __syncthreads();

    const int hin = tx >> 6;
    u64 acc[4] = {0ull, 0ull, 0ull, 0ull};
    const float* wc = wv + (size_t)dr0 * DD + c0 + tx;
#pragma unroll 16
    for (int dd = 0; dd < 128; dd += 2) {
        float w0 = wc[(size_t)dd * DD];
        float w1 = wc[(size_t)(dd + 1) * DD];
        u64 w2 = pack2(w0, w1);
#pragma unroll
        for (int bb = 0; bb < 4; bb++) {
            u64 s2 = *(const u64*)&sw[bb][hin][dd];
            fma2(acc[bb], s2, w2);
        }
    }
#pragma unroll
    for (int bb = 0; bb < 4; bb++) {
        float lo, hi; unpack2(acc[bb], lo, hi);
        atomicAdd(&out[(size_t)(b0 + bb) * DD + c0 + tx], lo + hi);
    }
}

// ---------------------------------------------------------------------------
// Four-stream quarter-batch pipeline:
//   s0(default): qproj -> [e0]
//   each stream q (q=0 default, q=1..3 extra): [wait e0] uproj(q) ->
//       scores(q) -> wpart(q) -> oproj(q) -> [eq for q>0]
//   s0: [wait e1,e2,e3]
// All per-quarter state is b-partitioned: no cross-stream dependencies.
// Streams/events lazily created once; identical per-call work (capture-legal).
// ---------------------------------------------------------------------------
extern "C" void kernel_launch(void* const* d_in, const int* in_sizes, int n_in,
                              void* d_out, int out_size) {
    const float* query = (const float*)d_in[0];
    const float* key   = (const float*)d_in[1];
    const float* value = (const float*)d_in[2];
    const float* wq    = (const float*)d_in[3];
    const float* wk    = (const float*)d_in[4];
    const float* wv    = (const float*)d_in[5];
    float* out = (float*)d_out;

    static cudaStream_t st[4] = {nullptr, nullptr, nullptr, nullptr};
    static cudaEvent_t  e0 = nullptr, ej[4] = {nullptr, nullptr, nullptr, nullptr};
    if (st[1] == nullptr) {
        st[0] = 0;   // default stream carries quarter 0
        for (int q = 1; q < 4; q++)
            cudaStreamCreateWithFlags(&st[q], cudaStreamNonBlocking);
        cudaEventCreateWithFlags(&e0, cudaEventDisableTiming);
        for (int q = 1; q < 4; q++)
            cudaEventCreateWithFlags(&ej[q], cudaEventDisableTiming);
    }

    k_qproj<<<dim3(8, 8, 8), 128>>>(query, wq, out);
    cudaEventRecord(e0, 0);
    for (int q = 1; q < 4; q++) cudaStreamWaitEvent(st[q], e0, 0);

    for (int q = 0; q < 4; q++) {
        const int boff = q * 8;
        k_uproj <<<dim3(8, HH),   128, 0, st[q]>>>(wk, boff);
        k_scores<<<dim3(16, 8),   64,  0, st[q]>>>(key, boff);
        k_wpart <<<dim3(2, 8, 8), 128, 0, st[q]>>>(value, boff);
        k_oproj <<<dim3(8, 2, 8), 128, 0, st[q]>>>(wv, out, q * 2);
        if (q > 0) cudaEventRecord(ej[q], st[q]);
    }
    for (int q = 1; q < 4; q++) cudaStreamWaitEvent(0, ej[q], 0);
}